// round 1
// baseline (speedup 1.0000x reference)
#include <cuda_runtime.h>
#include <cstdint>

#define TT 2048
#define BB 256

// Scratch: alpha_t for all (batch, t): [BB][TT][32] float2 (=64 states) = 134MB
__device__ float2 g_alpha[(size_t)BB * TT * 32];

__device__ __forceinline__ float warp_sum(float v) {
#pragma unroll
    for (int o = 16; o; o >>= 1) v += __shfl_xor_sync(0xffffffffu, v, o);
    return v;
}

// sign = 1 - 2*((popc(s&mask) ^ bit) & 1)
__device__ __forceinline__ float sg(int s, int mask, int bit) {
    return 1.0f - 2.0f * (float)((__popc(s & mask) ^ bit) & 1);
}

// ---------------------------------------------------------------------------
// Forward: one warp per batch row. Lane L carries alpha[2L], alpha[2L+1].
// Stores alpha (pre-update carry, == reference "alphas[t]") for every t.
// ---------------------------------------------------------------------------
__global__ __launch_bounds__(32, 1)
void fwd_kernel(const float* __restrict__ llr_ch, const float* __restrict__ llr_a) {
    const int b = blockIdx.x;
    const int L = threadIdx.x;
    const float* ch = llr_ch + (size_t)b * (2 * TT);
    const float* la = llr_a + (size_t)b * TT;
    float2* ga = g_alpha + (size_t)b * TT * 32 + L;

    // New states computed by lane L: j0=2L, j1=2L+1. Both have input bit = (2L)>>5.
    const int bit = (L >> 4) & 1;
    const int p0 = (2 * L) & 31;        // predecessor-pair lane for j0
    const int p1 = p0 + 1;              // predecessor-pair lane for j1
    const float cb = 1.0f - 2.0f * (float)bit;

    // Transition sign constants (s, bit): s in {2p0, 2p0+1, 2p1, 2p1+1}
    const int sA = 2 * p0, sB = 2 * p0 + 1, sC = 2 * p1, sD = 2 * p1 + 1;
    const float c0A = sg(sA, 57, bit), c1A = sg(sA, 27, bit);
    const float c0B = sg(sB, 57, bit), c1B = sg(sB, 27, bit);
    const float c0C = sg(sC, 57, bit), c1C = sg(sC, 27, bit);
    const float c0D = sg(sD, 57, bit), c1D = sg(sD, 27, bit);

    float a0 = (L == 0) ? 1.0f : 0.0f;
    float a1 = 0.0f;

    for (int t0 = 0; t0 < TT; t0 += 4) {
        // scale from group-start sum; its latency hides under the 4-step chain
        float S = warp_sum(a0 + a1);
        float r = __fdividef(1.0f, S);

        float l0v[4], l1v[4], lav[4];
#pragma unroll
        for (int k = 0; k < 4; k++) {
            int t = t0 + k;
            l0v[k] = __ldg(ch + 2 * t);
            l1v[k] = __ldg(ch + 2 * t + 1);
            lav[k] = __ldg(la + t);
        }
#pragma unroll
        for (int k = 0; k < 4; k++) {
            int t = t0 + k;
            ga[(size_t)t * 32] = make_float2(a0, a1);   // alphas[t] (any uniform scale ok)

            float gA = __expf(0.5f * (c0A * l0v[k] + c1A * l1v[k] + cb * lav[k]));
            float gB = __expf(0.5f * (c0B * l0v[k] + c1B * l1v[k] + cb * lav[k]));
            float gC = __expf(0.5f * (c0C * l0v[k] + c1C * l1v[k] + cb * lav[k]));
            float gD = __expf(0.5f * (c0D * l0v[k] + c1D * l1v[k] + cb * lav[k]));

            float pa0 = __shfl_sync(0xffffffffu, a0, p0);
            float pa1 = __shfl_sync(0xffffffffu, a1, p0);
            float qa0 = __shfl_sync(0xffffffffu, a0, p1);
            float qa1 = __shfl_sync(0xffffffffu, a1, p1);

            a0 = fmaf(gB, pa1, gA * pa0);
            a1 = fmaf(gD, qa1, gC * qa0);
        }
        a0 *= r; a1 *= r;
    }
}

// ---------------------------------------------------------------------------
// Backward + LLR: one warp per batch row. Lane L carries beta[2L], beta[2L+1].
// Successors of both 2L and 2L+1 are states L (b=0) and L+32 (b=1).
// ---------------------------------------------------------------------------
__global__ __launch_bounds__(32, 1)
void bwd_kernel(const float* __restrict__ llr_ch, const float* __restrict__ llr_a,
                float* __restrict__ out) {
    const int b = blockIdx.x;
    const int L = threadIdx.x;
    const float* ch = llr_ch + (size_t)b * (2 * TT);
    const float* la = llr_a + (size_t)b * TT;
    const float2* ga = g_alpha + (size_t)b * TT * 32 + L;
    float* ob = out + (size_t)b * TT;

    // Transition sign constants for (s=2L / 2L+1, bit=0/1)
    const float c00 = sg(2 * L, 57, 0), c01 = sg(2 * L, 27, 0);       // (2L,   0)
    const float d00 = sg(2 * L, 57, 1), d01 = sg(2 * L, 27, 1);       // (2L,   1)
    const float c10 = sg(2 * L + 1, 57, 0), c11 = sg(2 * L + 1, 27, 0); // (2L+1, 0)
    const float d10 = sg(2 * L + 1, 57, 1), d11 = sg(2 * L + 1, 27, 1); // (2L+1, 1)

    // beta_next[L] lives at lane L>>1 (reg L&1); beta_next[L+32] at lane 16+(L>>1)
    const int srcL = L >> 1;
    const int srcH = 16 + (L >> 1);
    const bool odd = (L & 1) != 0;

    float b0 = 1.0f / 64.0f, b1 = 1.0f / 64.0f;   // beta_T (uniform; scale cancels)

    for (int t0 = TT - 4; t0 >= 0; t0 -= 4) {
        float S = warp_sum(b0 + b1);
        float r = __fdividef(1.0f, S);

        float l0v[4], l1v[4], lav[4];
        float2 av[4];
#pragma unroll
        for (int k = 0; k < 4; k++) {
            int t = t0 + k;
            l0v[k] = __ldg(ch + 2 * t);
            l1v[k] = __ldg(ch + 2 * t + 1);
            lav[k] = __ldg(la + t);
            av[k] = ga[(size_t)t * 32];
        }
#pragma unroll
        for (int kk = 0; kk < 4; kk++) {
            int k = 3 - kk;           // process t descending
            int t = t0 + k;

            float g00 = __expf(0.5f * (c00 * l0v[k] + c01 * l1v[k] + lav[k]));
            float g01 = __expf(0.5f * (d00 * l0v[k] + d01 * l1v[k] - lav[k]));
            float g10 = __expf(0.5f * (c10 * l0v[k] + c11 * l1v[k] + lav[k]));
            float g11 = __expf(0.5f * (d10 * l0v[k] + d11 * l1v[k] - lav[k]));

            float xb0 = __shfl_sync(0xffffffffu, b0, srcL);
            float xb1 = __shfl_sync(0xffffffffu, b1, srcL);
            float bnL = odd ? xb1 : xb0;
            float yb0 = __shfl_sync(0xffffffffu, b0, srcH);
            float yb1 = __shfl_sync(0xffffffffu, b1, srcH);
            float bnH = odd ? yb1 : yb0;

            // beta update (critical path)
            float nb0 = fmaf(g01, bnH, g00 * bnL);
            float nb1 = fmaf(g11, bnH, g10 * bnL);

            // LLR extraction (off critical path)
            float J0 = bnL * fmaf(av[k].y, g10, av[k].x * g00);
            float J1 = bnH * fmaf(av[k].y, g11, av[k].x * g01);
            J0 = warp_sum(J0);
            J1 = warp_sum(J1);
            if (L == 0) ob[t] = __logf(J0) - __logf(J1);

            b0 = nb0; b1 = nb1;
        }
        b0 *= r; b1 *= r;
    }
}

extern "C" void kernel_launch(void* const* d_in, const int* in_sizes, int n_in,
                              void* d_out, int out_size) {
    const float* llr_ch = (const float*)d_in[0];   // [256, 4096]
    const float* llr_a  = (const float*)d_in[1];   // [256, 2048]
    float* out = (float*)d_out;                    // [256, 2048]

    fwd_kernel<<<BB, 32>>>(llr_ch, llr_a);
    bwd_kernel<<<BB, 32>>>(llr_ch, llr_a, out);
}

// round 2
// speedup vs baseline: 2.5017x; 2.5017x over previous
#include <cuda_runtime.h>
#include <cstdint>

#define TT 2048
#define BB 256

// Scratch: alpha_t and beta_{t+1} for all (batch, t).
// Layout: [BB][TT][32] float2  == [BB][TT][64] float, lane L <-> states 2L, 2L+1.
__device__ float2 g_alpha[(size_t)BB * TT * 32];
__device__ float2 g_beta [(size_t)BB * TT * 32];

__device__ __forceinline__ float warp_sum(float v) {
#pragma unroll
    for (int o = 16; o; o >>= 1) v += __shfl_xor_sync(0xffffffffu, v, o);
    return v;
}

// sign = 1 - 2*((popc(s&mask) ^ bit) & 1)
__device__ __forceinline__ float sg(int s, int mask, int bit) {
    return 1.0f - 2.0f * (float)((__popc(s & mask) ^ bit) & 1);
}

// ---------------------------------------------------------------------------
// Forward body: lane L carries alpha[2L], alpha[2L+1]; stores alphas[t].
// ---------------------------------------------------------------------------
__device__ void fwd_body(int b, int L,
                         const float* __restrict__ llr_ch,
                         const float* __restrict__ llr_a) {
    const float* ch = llr_ch + (size_t)b * (2 * TT);
    const float* la = llr_a + (size_t)b * TT;
    float2* ga = g_alpha + (size_t)b * TT * 32 + L;

    const int bit = (L >> 4) & 1;
    const int p0 = (2 * L) & 31;
    const int p1 = p0 + 1;
    const float cb = 1.0f - 2.0f * (float)bit;

    const int sA = 2 * p0, sB = 2 * p0 + 1, sC = 2 * p1, sD = 2 * p1 + 1;
    const float c0A = sg(sA, 57, bit), c1A = sg(sA, 27, bit);
    const float c0B = sg(sB, 57, bit), c1B = sg(sB, 27, bit);
    const float c0C = sg(sC, 57, bit), c1C = sg(sC, 27, bit);
    const float c0D = sg(sD, 57, bit), c1D = sg(sD, 27, bit);

    float a0 = (L == 0) ? 1.0f : 0.0f;
    float a1 = 0.0f;

    for (int t0 = 0; t0 < TT; t0 += 4) {
        float S = warp_sum(a0 + a1);
        float r = __fdividef(1.0f, S);

        float l0v[4], l1v[4], lav[4];
#pragma unroll
        for (int k = 0; k < 4; k++) {
            int t = t0 + k;
            l0v[k] = __ldg(ch + 2 * t);
            l1v[k] = __ldg(ch + 2 * t + 1);
            lav[k] = __ldg(la + t);
        }
#pragma unroll
        for (int k = 0; k < 4; k++) {
            int t = t0 + k;
            ga[(size_t)t * 32] = make_float2(a0, a1);

            float gA = __expf(0.5f * (c0A * l0v[k] + c1A * l1v[k] + cb * lav[k]));
            float gB = __expf(0.5f * (c0B * l0v[k] + c1B * l1v[k] + cb * lav[k]));
            float gC = __expf(0.5f * (c0C * l0v[k] + c1C * l1v[k] + cb * lav[k]));
            float gD = __expf(0.5f * (c0D * l0v[k] + c1D * l1v[k] + cb * lav[k]));

            float pa0 = __shfl_sync(0xffffffffu, a0, p0);
            float pa1 = __shfl_sync(0xffffffffu, a1, p0);
            float qa0 = __shfl_sync(0xffffffffu, a0, p1);
            float qa1 = __shfl_sync(0xffffffffu, a1, p1);

            a0 = fmaf(gB, pa1, gA * pa0);
            a1 = fmaf(gD, qa1, gC * qa0);
        }
        a0 *= r; a1 *= r;
    }
}

// ---------------------------------------------------------------------------
// Backward body (beta recursion ONLY): lane L carries beta[2L], beta[2L+1].
// Stores beta_{t+1} (the pre-update carry) at slot t.
// ---------------------------------------------------------------------------
__device__ void beta_body(int b, int L,
                          const float* __restrict__ llr_ch,
                          const float* __restrict__ llr_a) {
    const float* ch = llr_ch + (size_t)b * (2 * TT);
    const float* la = llr_a + (size_t)b * TT;
    float2* gb = g_beta + (size_t)b * TT * 32 + L;

    const float c00 = sg(2 * L, 57, 0), c01 = sg(2 * L, 27, 0);
    const float d00 = sg(2 * L, 57, 1), d01 = sg(2 * L, 27, 1);
    const float c10 = sg(2 * L + 1, 57, 0), c11 = sg(2 * L + 1, 27, 0);
    const float d10 = sg(2 * L + 1, 57, 1), d11 = sg(2 * L + 1, 27, 1);

    const int srcL = L >> 1;
    const int srcH = 16 + (L >> 1);
    const bool odd = (L & 1) != 0;

    float b0 = 1.0f / 64.0f, b1 = 1.0f / 64.0f;

    for (int t0 = TT - 4; t0 >= 0; t0 -= 4) {
        float S = warp_sum(b0 + b1);
        float r = __fdividef(1.0f, S);

        float l0v[4], l1v[4], lav[4];
#pragma unroll
        for (int k = 0; k < 4; k++) {
            int t = t0 + k;
            l0v[k] = __ldg(ch + 2 * t);
            l1v[k] = __ldg(ch + 2 * t + 1);
            lav[k] = __ldg(la + t);
        }
#pragma unroll
        for (int kk = 0; kk < 4; kk++) {
            int k = 3 - kk;
            int t = t0 + k;

            // store beta_{t+1} carry for the LLR pass
            gb[(size_t)t * 32] = make_float2(b0, b1);

            float g00 = __expf(0.5f * (c00 * l0v[k] + c01 * l1v[k] + lav[k]));
            float g01 = __expf(0.5f * (d00 * l0v[k] + d01 * l1v[k] - lav[k]));
            float g10 = __expf(0.5f * (c10 * l0v[k] + c11 * l1v[k] + lav[k]));
            float g11 = __expf(0.5f * (d10 * l0v[k] + d11 * l1v[k] - lav[k]));

            float xb0 = __shfl_sync(0xffffffffu, b0, srcL);
            float xb1 = __shfl_sync(0xffffffffu, b1, srcL);
            float bnL = odd ? xb1 : xb0;
            float yb0 = __shfl_sync(0xffffffffu, b0, srcH);
            float yb1 = __shfl_sync(0xffffffffu, b1, srcH);
            float bnH = odd ? yb1 : yb0;

            b0 = fmaf(g01, bnH, g00 * bnL);
            b1 = fmaf(g11, bnH, g10 * bnL);
        }
        b0 *= r; b1 *= r;
    }
}

// Kernel A: fwd and beta recursions run concurrently (independent).
__global__ __launch_bounds__(32, 1)
void recursions_kernel(const float* __restrict__ llr_ch, const float* __restrict__ llr_a) {
    if (blockIdx.x < BB) fwd_body(blockIdx.x, threadIdx.x, llr_ch, llr_a);
    else                 beta_body(blockIdx.x - BB, threadIdx.x, llr_ch, llr_a);
}

// ---------------------------------------------------------------------------
// Kernel B: LLR extraction, one warp per (b, t). Fully parallel.
//   J0 = sum_L beta_{t+1}[L]   * (alpha_t[2L]*g00 + alpha_t[2L+1]*g10)
//   J1 = sum_L beta_{t+1}[L+32]* (alpha_t[2L]*g01 + alpha_t[2L+1]*g11)
// ---------------------------------------------------------------------------
__global__ __launch_bounds__(256)
void llr_kernel(const float* __restrict__ llr_ch, const float* __restrict__ llr_a,
                float* __restrict__ out) {
    const int L = threadIdx.x & 31;
    const unsigned wid = (blockIdx.x * (blockDim.x >> 5)) + (threadIdx.x >> 5);
    const int b = wid >> 11;          // 2048 t's per batch row
    const int t = wid & 2047;

    const float l0 = __ldg(llr_ch + (size_t)b * (2 * TT) + 2 * t);
    const float l1 = __ldg(llr_ch + (size_t)b * (2 * TT) + 2 * t + 1);
    const float la = __ldg(llr_a + (size_t)b * TT + t);

    const float2 a = g_alpha[(size_t)b * TT * 32 + (size_t)t * 32 + L];
    const float* bt = (const float*)(g_beta + (size_t)b * TT * 32 + (size_t)t * 32);
    const float bnL = bt[L];
    const float bnH = bt[L + 32];

    const float c00 = sg(2 * L, 57, 0), c01 = sg(2 * L, 27, 0);
    const float d00 = sg(2 * L, 57, 1), d01 = sg(2 * L, 27, 1);
    const float c10 = sg(2 * L + 1, 57, 0), c11 = sg(2 * L + 1, 27, 0);
    const float d10 = sg(2 * L + 1, 57, 1), d11 = sg(2 * L + 1, 27, 1);

    const float g00 = __expf(0.5f * (c00 * l0 + c01 * l1 + la));
    const float g01 = __expf(0.5f * (d00 * l0 + d01 * l1 - la));
    const float g10 = __expf(0.5f * (c10 * l0 + c11 * l1 + la));
    const float g11 = __expf(0.5f * (d10 * l0 + d11 * l1 - la));

    float J0 = bnL * fmaf(a.y, g10, a.x * g00);
    float J1 = bnH * fmaf(a.y, g11, a.x * g01);
    J0 = warp_sum(J0);
    J1 = warp_sum(J1);

    if (L == 0) out[(size_t)b * TT + t] = __logf(J0) - __logf(J1);
}

extern "C" void kernel_launch(void* const* d_in, const int* in_sizes, int n_in,
                              void* d_out, int out_size) {
    const float* llr_ch = (const float*)d_in[0];   // [256, 4096]
    const float* llr_a  = (const float*)d_in[1];   // [256, 2048]
    float* out = (float*)d_out;                    // [256, 2048]

    recursions_kernel<<<2 * BB, 32>>>(llr_ch, llr_a);

    // one warp per (b, t): 256*2048 warps, 8 warps per block
    llr_kernel<<<(BB * TT) / 8, 256>>>(llr_ch, llr_a, out);
}

// round 3
// speedup vs baseline: 2.7089x; 1.0828x over previous
#include <cuda_runtime.h>
#include <cuda_fp16.h>
#include <cstdint>

#define TT 2048
#define BB 256
#define CH 128
#define NCHUNK (TT / CH)   // 16

// Checkpoints: alpha carry at t = c*CH, beta carry (= beta_{t+1}) at t = (c+1)*CH-1.
// Lane L holds states 2L, 2L+1.  2 x 1MB total.
__device__ float2 g_fck[BB][NCHUNK][32];
__device__ float2 g_bck[BB][NCHUNK][32];

__device__ __forceinline__ float warp_sum(float v) {
#pragma unroll
    for (int o = 16; o; o >>= 1) v += __shfl_xor_sync(0xffffffffu, v, o);
    return v;
}

// sign = 1 - 2*((popc(s&mask) ^ bit) & 1)
__device__ __forceinline__ float sg(int s, int mask, int bit) {
    return 1.0f - 2.0f * (float)((__popc(s & mask) ^ bit) & 1);
}

// ---------------------------------------------------------------------------
// Pass 1: full-length recursions, storing only boundary checkpoints.
// Blocks 0..BB-1: forward alpha.  Blocks BB..2BB-1: backward beta.
// ---------------------------------------------------------------------------
__global__ __launch_bounds__(32, 1)
void ckpt_kernel(const float* __restrict__ llr_ch, const float* __restrict__ llr_a) {
    const int L = threadIdx.x;

    if (blockIdx.x < BB) {
        const int b = blockIdx.x;
        const float* ch = llr_ch + (size_t)b * (2 * TT);
        const float* la = llr_a + (size_t)b * TT;

        const int bit = (L >> 4) & 1;
        const int p0 = (2 * L) & 31;
        const int p1 = p0 + 1;
        const float cb = 1.0f - 2.0f * (float)bit;
        const int sA = 2 * p0, sB = 2 * p0 + 1, sC = 2 * p1, sD = 2 * p1 + 1;
        const float c0A = sg(sA, 57, bit), c1A = sg(sA, 27, bit);
        const float c0B = sg(sB, 57, bit), c1B = sg(sB, 27, bit);
        const float c0C = sg(sC, 57, bit), c1C = sg(sC, 27, bit);
        const float c0D = sg(sD, 57, bit), c1D = sg(sD, 27, bit);

        float a0 = (L == 0) ? 1.0f : 0.0f;
        float a1 = 0.0f;

        for (int t0 = 0; t0 < TT; t0 += 4) {
            if ((t0 & (CH - 1)) == 0)
                g_fck[b][t0 >> 7][L] = make_float2(a0, a1);

            float S = warp_sum(a0 + a1);
            float r = __fdividef(1.0f, S);

            float l0v[4], l1v[4], lav[4];
#pragma unroll
            for (int k = 0; k < 4; k++) {
                int t = t0 + k;
                l0v[k] = __ldg(ch + 2 * t);
                l1v[k] = __ldg(ch + 2 * t + 1);
                lav[k] = __ldg(la + t);
            }
#pragma unroll
            for (int k = 0; k < 4; k++) {
                float gA = __expf(0.5f * (c0A * l0v[k] + c1A * l1v[k] + cb * lav[k]));
                float gB = __expf(0.5f * (c0B * l0v[k] + c1B * l1v[k] + cb * lav[k]));
                float gC = __expf(0.5f * (c0C * l0v[k] + c1C * l1v[k] + cb * lav[k]));
                float gD = __expf(0.5f * (c0D * l0v[k] + c1D * l1v[k] + cb * lav[k]));

                float pa0 = __shfl_sync(0xffffffffu, a0, p0);
                float pa1 = __shfl_sync(0xffffffffu, a1, p0);
                float qa0 = __shfl_sync(0xffffffffu, a0, p1);
                float qa1 = __shfl_sync(0xffffffffu, a1, p1);

                a0 = fmaf(gB, pa1, gA * pa0);
                a1 = fmaf(gD, qa1, gC * qa0);
            }
            a0 *= r; a1 *= r;
        }
    } else {
        const int b = blockIdx.x - BB;
        const float* ch = llr_ch + (size_t)b * (2 * TT);
        const float* la = llr_a + (size_t)b * TT;

        const float c00 = sg(2 * L, 57, 0), c01 = sg(2 * L, 27, 0);
        const float d00 = sg(2 * L, 57, 1), d01 = sg(2 * L, 27, 1);
        const float c10 = sg(2 * L + 1, 57, 0), c11 = sg(2 * L + 1, 27, 0);
        const float d10 = sg(2 * L + 1, 57, 1), d11 = sg(2 * L + 1, 27, 1);

        const int srcL = L >> 1;
        const int srcH = 16 + (L >> 1);
        const bool odd = (L & 1) != 0;

        float b0 = 1.0f / 64.0f, b1 = 1.0f / 64.0f;

        for (int t0 = TT - 4; t0 >= 0; t0 -= 4) {
            // first processed step of this group is t0+3
            if ((t0 & (CH - 1)) == CH - 4)
                g_bck[b][t0 >> 7][L] = make_float2(b0, b1);

            float S = warp_sum(b0 + b1);
            float r = __fdividef(1.0f, S);

            float l0v[4], l1v[4], lav[4];
#pragma unroll
            for (int k = 0; k < 4; k++) {
                int t = t0 + k;
                l0v[k] = __ldg(ch + 2 * t);
                l1v[k] = __ldg(ch + 2 * t + 1);
                lav[k] = __ldg(la + t);
            }
#pragma unroll
            for (int kk = 0; kk < 4; kk++) {
                int k = 3 - kk;
                float g00 = __expf(0.5f * (c00 * l0v[k] + c01 * l1v[k] + lav[k]));
                float g01 = __expf(0.5f * (d00 * l0v[k] + d01 * l1v[k] - lav[k]));
                float g10 = __expf(0.5f * (c10 * l0v[k] + c11 * l1v[k] + lav[k]));
                float g11 = __expf(0.5f * (d10 * l0v[k] + d11 * l1v[k] - lav[k]));

                float xb0 = __shfl_sync(0xffffffffu, b0, srcL);
                float xb1 = __shfl_sync(0xffffffffu, b1, srcL);
                float bnL = odd ? xb1 : xb0;
                float yb0 = __shfl_sync(0xffffffffu, b0, srcH);
                float yb1 = __shfl_sync(0xffffffffu, b1, srcH);
                float bnH = odd ? yb1 : yb0;

                b0 = fmaf(g01, bnH, g00 * bnL);
                b1 = fmaf(g11, bnH, g10 * bnL);
            }
            b0 *= r; b1 *= r;
        }
    }
}

// ---------------------------------------------------------------------------
// Pass 2: per (batch, chunk) block. Warp0 recomputes alpha, warp1 beta, both
// into fp16 smem (per-t scale arbitrary — cancels in the LLR). Then 8 warps
// do the LLR extraction from smem. No DRAM scratch.
// ---------------------------------------------------------------------------
__global__ __launch_bounds__(256, 1)
void chunk_kernel(const float* __restrict__ llr_ch, const float* __restrict__ llr_a,
                  float* __restrict__ out) {
    __shared__ __half2 sA[CH][32];
    __shared__ __half2 sBt[CH][32];
    __shared__ float sO[CH];

    const int c = blockIdx.x & (NCHUNK - 1);
    const int b = blockIdx.x >> 4;
    const int tb = c * CH;
    const int w = threadIdx.x >> 5;
    const int L = threadIdx.x & 31;

    const float* ch = llr_ch + (size_t)b * (2 * TT);
    const float* la = llr_a + (size_t)b * TT;

    if (w == 0) {
        // ---- alpha chunk ----
        const int bit = (L >> 4) & 1;
        const int p0 = (2 * L) & 31;
        const int p1 = p0 + 1;
        const float cb = 1.0f - 2.0f * (float)bit;
        const int ssA = 2 * p0, ssB = 2 * p0 + 1, ssC = 2 * p1, ssD = 2 * p1 + 1;
        const float c0A = sg(ssA, 57, bit), c1A = sg(ssA, 27, bit);
        const float c0B = sg(ssB, 57, bit), c1B = sg(ssB, 27, bit);
        const float c0C = sg(ssC, 57, bit), c1C = sg(ssC, 27, bit);
        const float c0D = sg(ssD, 57, bit), c1D = sg(ssD, 27, bit);

        float2 seed = g_fck[b][c][L];
        float a0 = seed.x, a1 = seed.y;

        for (int g = 0; g < CH; g += 4) {
            float S = warp_sum(a0 + a1);
            float r = __fdividef(1.0f, S);

            float l0v[4], l1v[4], lav[4], u0[4], u1[4];
#pragma unroll
            for (int k = 0; k < 4; k++) {
                int t = tb + g + k;
                l0v[k] = __ldg(ch + 2 * t);
                l1v[k] = __ldg(ch + 2 * t + 1);
                lav[k] = __ldg(la + t);
            }
#pragma unroll
            for (int k = 0; k < 4; k++) {
                u0[k] = a0; u1[k] = a1;
                float gA = __expf(0.5f * (c0A * l0v[k] + c1A * l1v[k] + cb * lav[k]));
                float gB = __expf(0.5f * (c0B * l0v[k] + c1B * l1v[k] + cb * lav[k]));
                float gC = __expf(0.5f * (c0C * l0v[k] + c1C * l1v[k] + cb * lav[k]));
                float gD = __expf(0.5f * (c0D * l0v[k] + c1D * l1v[k] + cb * lav[k]));
                float pa0 = __shfl_sync(0xffffffffu, a0, p0);
                float pa1 = __shfl_sync(0xffffffffu, a1, p0);
                float qa0 = __shfl_sync(0xffffffffu, a0, p1);
                float qa1 = __shfl_sync(0xffffffffu, a1, p1);
                a0 = fmaf(gB, pa1, gA * pa0);
                a1 = fmaf(gD, qa1, gC * qa0);
            }
#pragma unroll
            for (int k = 0; k < 4; k++)
                sA[g + k][L] = __floats2half2_rn(fminf(u0[k] * r, 60000.0f),
                                                 fminf(u1[k] * r, 60000.0f));
            a0 *= r; a1 *= r;
        }
    } else if (w == 1) {
        // ---- beta chunk ----
        const float c00 = sg(2 * L, 57, 0), c01 = sg(2 * L, 27, 0);
        const float d00 = sg(2 * L, 57, 1), d01 = sg(2 * L, 27, 1);
        const float c10 = sg(2 * L + 1, 57, 0), c11 = sg(2 * L + 1, 27, 0);
        const float d10 = sg(2 * L + 1, 57, 1), d11 = sg(2 * L + 1, 27, 1);
        const int srcL = L >> 1;
        const int srcH = 16 + (L >> 1);
        const bool odd = (L & 1) != 0;

        float2 seed = g_bck[b][c][L];
        float b0 = seed.x, b1 = seed.y;

        for (int g = CH - 4; g >= 0; g -= 4) {
            float S = warp_sum(b0 + b1);
            float r = __fdividef(1.0f, S);

            float l0v[4], l1v[4], lav[4], u0[4], u1[4];
#pragma unroll
            for (int k = 0; k < 4; k++) {
                int t = tb + g + k;
                l0v[k] = __ldg(ch + 2 * t);
                l1v[k] = __ldg(ch + 2 * t + 1);
                lav[k] = __ldg(la + t);
            }
#pragma unroll
            for (int kk = 0; kk < 4; kk++) {
                int k = 3 - kk;
                u0[k] = b0; u1[k] = b1;   // carry = beta_{t+1} at slot t
                float g00 = __expf(0.5f * (c00 * l0v[k] + c01 * l1v[k] + lav[k]));
                float g01 = __expf(0.5f * (d00 * l0v[k] + d01 * l1v[k] - lav[k]));
                float g10 = __expf(0.5f * (c10 * l0v[k] + c11 * l1v[k] + lav[k]));
                float g11 = __expf(0.5f * (d10 * l0v[k] + d11 * l1v[k] - lav[k]));
                float xb0 = __shfl_sync(0xffffffffu, b0, srcL);
                float xb1 = __shfl_sync(0xffffffffu, b1, srcL);
                float bnL = odd ? xb1 : xb0;
                float yb0 = __shfl_sync(0xffffffffu, b0, srcH);
                float yb1 = __shfl_sync(0xffffffffu, b1, srcH);
                float bnH = odd ? yb1 : yb0;
                b0 = fmaf(g01, bnH, g00 * bnL);
                b1 = fmaf(g11, bnH, g10 * bnL);
            }
#pragma unroll
            for (int k = 0; k < 4; k++)
                sBt[g + k][L] = __floats2half2_rn(fminf(u0[k] * r, 60000.0f),
                                                  fminf(u1[k] * r, 60000.0f));
            b0 *= r; b1 *= r;
        }
    }

    __syncthreads();

    // ---- LLR extraction: 8 warps x 16 t ----
    const float c00 = sg(2 * L, 57, 0), c01 = sg(2 * L, 27, 0);
    const float d00 = sg(2 * L, 57, 1), d01 = sg(2 * L, 27, 1);
    const float c10 = sg(2 * L + 1, 57, 0), c11 = sg(2 * L + 1, 27, 0);
    const float d10 = sg(2 * L + 1, 57, 1), d11 = sg(2 * L + 1, 27, 1);
    // gamma index: bit2 <-> sign of l0, bit1 <-> sign of l1, bit0 <-> sign of la
    const int j00 = (c00 < 0.f ? 4 : 0) | (c01 < 0.f ? 2 : 0);
    const int j01 = (d00 < 0.f ? 4 : 0) | (d01 < 0.f ? 2 : 0) | 1;
    const int j10 = (c10 < 0.f ? 4 : 0) | (c11 < 0.f ? 2 : 0);
    const int j11 = (d10 < 0.f ? 4 : 0) | (d11 < 0.f ? 2 : 0) | 1;
    const int jj = L & 7;
    const float e0 = (jj & 4) ? -0.5f : 0.5f;
    const float e1 = (jj & 2) ? -0.5f : 0.5f;
    const float eb = (jj & 1) ? -0.5f : 0.5f;
    const __half* bh = (const __half*)sBt;

#pragma unroll 4
    for (int i = 0; i < 16; i++) {
        int tl = w * 16 + i;
        int t = tb + tl;
        float l0 = __ldg(ch + 2 * t);
        float l1 = __ldg(ch + 2 * t + 1);
        float laa = __ldg(la + t);

        float E = __expf(fmaf(e0, l0, fmaf(e1, l1, eb * laa)));
        float g00 = __shfl_sync(0xffffffffu, E, j00);
        float g01 = __shfl_sync(0xffffffffu, E, j01);
        float g10 = __shfl_sync(0xffffffffu, E, j10);
        float g11 = __shfl_sync(0xffffffffu, E, j11);

        float2 a = __half22float2(sA[tl][L]);
        float bnL = __half2float(bh[tl * 64 + L]);
        float bnH = __half2float(bh[tl * 64 + 32 + L]);

        float J0 = warp_sum(bnL * fmaf(a.y, g10, a.x * g00));
        float J1 = warp_sum(bnH * fmaf(a.y, g11, a.x * g01));
        if (L == 0) sO[tl] = __logf(J0) - __logf(J1);
    }

    __syncthreads();
    if (w == 0) {
#pragma unroll
        for (int i = 0; i < CH / 32; i++)
            out[(size_t)b * TT + tb + i * 32 + L] = sO[i * 32 + L];
    }
}

extern "C" void kernel_launch(void* const* d_in, const int* in_sizes, int n_in,
                              void* d_out, int out_size) {
    const float* llr_ch = (const float*)d_in[0];   // [256, 4096]
    const float* llr_a  = (const float*)d_in[1];   // [256, 2048]
    float* out = (float*)d_out;                    // [256, 2048]

    ckpt_kernel<<<2 * BB, 32>>>(llr_ch, llr_a);
    chunk_kernel<<<BB * NCHUNK, 256>>>(llr_ch, llr_a, out);
}

// round 4
// speedup vs baseline: 2.8733x; 1.0607x over previous
#include <cuda_runtime.h>
#include <cuda_fp16.h>
#include <cstdint>

#define TT 2048
#define BB 256
#define CH 64
#define NCHUNK (TT / CH)   // 32

// Checkpoints: alpha carry at t = c*CH, beta carry (= beta_{(c+1)*CH}).
__device__ float2 g_fck[BB][NCHUNK][32];
__device__ float2 g_bck[BB][NCHUNK][32];

__device__ __forceinline__ float warp_sum(float v) {
#pragma unroll
    for (int o = 16; o; o >>= 1) v += __shfl_xor_sync(0xffffffffu, v, o);
    return v;
}

// gamma(s,b) = exp(0.5*(c0*l0 + c1*l1 + (1-2b)*la)); only 8 distinct values per t.
// Index: bit2 = l0 sign neg, bit1 = l1 sign neg, bit0 = la sign neg (== b).
__device__ __forceinline__ int gidx(int s, int b) {
    int b2 = (__popc(s & 57) ^ b) & 1;
    int b1 = (__popc(s & 27) ^ b) & 1;
    return (b2 << 2) | (b1 << 1) | b;
}

// ---------------------------------------------------------------------------
// Pass 1: full-length recursions with 2-step trellis fusion; store only
// per-chunk boundary checkpoints. Blocks 0..BB-1: alpha. BB..2BB-1: beta.
// ---------------------------------------------------------------------------
__global__ __launch_bounds__(32, 1)
void ckpt_kernel(const float* __restrict__ llr_ch, const float* __restrict__ llr_a) {
    const int L = threadIdx.x;
    const int jj = L & 7;
    const float e0 = (jj & 4) ? -0.5f : 0.5f;
    const float e1 = (jj & 2) ? -0.5f : 0.5f;
    const float eb = (jj & 1) ? -0.5f : 0.5f;

    if (blockIdx.x < BB) {
        // ================= forward (alpha), fused 2-step ====================
        const int b = blockIdx.x;
        const float* ch = llr_ch + (size_t)b * (2 * TT);
        const float* la = llr_a + (size_t)b * TT;

        const int bit = L >> 4;
        const int p0 = (2 * L) & 31, p1 = p0 + 1;
        const int q0 = (2 * p0) & 31, q2 = (2 * p1) & 31;
        const int q1 = q0 + 1, q3 = q2 + 1;
        const int bm0 = p0 >> 4, bm1 = p1 >> 4;
        // gamma_{t+1} (outer) selects
        const int iG0 = gidx(2 * p0, bit), iG1 = gidx(2 * p0 + 1, bit);
        const int iG2 = gidx(2 * p1, bit), iG3 = gidx(2 * p1 + 1, bit);
        // gamma_t (inner) selects
        const int i00 = gidx(2 * q0, bm0),     i01 = gidx(2 * q0 + 1, bm0);
        const int i02 = gidx(2 * q0 + 2, bm0), i03 = gidx(2 * q0 + 3, bm0);
        const int i10 = gidx(2 * q2, bm1),     i11 = gidx(2 * q2 + 1, bm1);
        const int i12 = gidx(2 * q2 + 2, bm1), i13 = gidx(2 * q2 + 3, bm1);

        float a0 = (L == 0) ? 1.0f : 0.0f;
        float a1 = 0.0f;

        for (int t0 = 0; t0 < TT; t0 += 4) {
            if ((t0 & (CH - 1)) == 0)
                g_fck[b][t0 >> 6][L] = make_float2(a0, a1);

            float S = warp_sum(a0 + a1);
            float r = __fdividef(1.0f, S);

            float E[4];
#pragma unroll
            for (int k = 0; k < 4; k++) {
                int t = t0 + k;
                float l0 = __ldg(ch + 2 * t);
                float l1 = __ldg(ch + 2 * t + 1);
                float laa = __ldg(la + t);
                E[k] = __expf(fmaf(e0, l0, fmaf(e1, l1, eb * laa)));
            }
#pragma unroll
            for (int it = 0; it < 2; it++) {
                float E0 = E[2 * it], E1 = E[2 * it + 1];
                float G0 = __shfl_sync(0xffffffffu, E1, iG0);
                float G1 = __shfl_sync(0xffffffffu, E1, iG1);
                float G2 = __shfl_sync(0xffffffffu, E1, iG2);
                float G3 = __shfl_sync(0xffffffffu, E1, iG3);
                float g00 = __shfl_sync(0xffffffffu, E0, i00);
                float g01 = __shfl_sync(0xffffffffu, E0, i01);
                float g02 = __shfl_sync(0xffffffffu, E0, i02);
                float g03 = __shfl_sync(0xffffffffu, E0, i03);
                float g10 = __shfl_sync(0xffffffffu, E0, i10);
                float g11 = __shfl_sync(0xffffffffu, E0, i11);
                float g12 = __shfl_sync(0xffffffffu, E0, i12);
                float g13 = __shfl_sync(0xffffffffu, E0, i13);
                float w00 = G0 * g00, w01 = G0 * g01, w02 = G1 * g02, w03 = G1 * g03;
                float w10 = G2 * g10, w11 = G2 * g11, w12 = G3 * g12, w13 = G3 * g13;

                float x0 = __shfl_sync(0xffffffffu, a0, q0);
                float x1 = __shfl_sync(0xffffffffu, a1, q0);
                float y0 = __shfl_sync(0xffffffffu, a0, q1);
                float y1 = __shfl_sync(0xffffffffu, a1, q1);
                float z0 = __shfl_sync(0xffffffffu, a0, q2);
                float z1 = __shfl_sync(0xffffffffu, a1, q2);
                float u0 = __shfl_sync(0xffffffffu, a0, q3);
                float u1 = __shfl_sync(0xffffffffu, a1, q3);

                a0 = fmaf(w01, x1, w00 * x0) + fmaf(w03, y1, w02 * y0);
                a1 = fmaf(w11, z1, w10 * z0) + fmaf(w13, u1, w12 * u0);
            }
            a0 *= r; a1 *= r;
        }
    } else {
        // ================= backward (beta), fused 2-step ====================
        const int b = blockIdx.x - BB;
        const float* ch = llr_ch + (size_t)b * (2 * TT);
        const float* la = llr_a + (size_t)b * TT;

        // inner gamma_{t+1} selects (successor states L, L+32)
        const int i_in0 = gidx(L, 0),      i_in1 = gidx(L, 1);
        const int i_in2 = gidx(L + 32, 0), i_in3 = gidx(L + 32, 1);
        // outer gamma_t selects (own states 2L, 2L+1)
        const int i_o00 = gidx(2 * L, 0),     i_o01 = gidx(2 * L, 1);
        const int i_o10 = gidx(2 * L + 1, 0), i_o11 = gidx(2 * L + 1, 1);
        // beta_{t+2} gather lanes, states r = {L>>1, 32+(L>>1), 16+(L>>1), 48+(L>>1)}
        const int m0 = L >> 2, m1 = 16 + (L >> 2), m2 = 8 + (L >> 2), m3 = 24 + (L >> 2);
        const bool sel = ((L >> 1) & 1) != 0;

        float b0 = 1.0f / 64.0f, b1 = 1.0f / 64.0f;

        for (int t0 = TT - 4; t0 >= 0; t0 -= 4) {
            if ((t0 & (CH - 1)) == CH - 4)
                g_bck[b][t0 >> 6][L] = make_float2(b0, b1);

            float S = warp_sum(b0 + b1);
            float r = __fdividef(1.0f, S);

            float E[4];
#pragma unroll
            for (int k = 0; k < 4; k++) {
                int t = t0 + k;
                float l0 = __ldg(ch + 2 * t);
                float l1 = __ldg(ch + 2 * t + 1);
                float laa = __ldg(la + t);
                E[k] = __expf(fmaf(e0, l0, fmaf(e1, l1, eb * laa)));
            }
#pragma unroll
            for (int it = 1; it >= 0; it--) {
                float Ein = E[2 * it + 1];   // gamma at later time (inner)
                float Eo  = E[2 * it];       // gamma at earlier time (outer)
                float gi0 = __shfl_sync(0xffffffffu, Ein, i_in0);
                float gi1 = __shfl_sync(0xffffffffu, Ein, i_in1);
                float gi2 = __shfl_sync(0xffffffffu, Ein, i_in2);
                float gi3 = __shfl_sync(0xffffffffu, Ein, i_in3);

                float p00 = __shfl_sync(0xffffffffu, b0, m0);
                float p01 = __shfl_sync(0xffffffffu, b1, m0);
                float p10 = __shfl_sync(0xffffffffu, b0, m1);
                float p11 = __shfl_sync(0xffffffffu, b1, m1);
                float p20 = __shfl_sync(0xffffffffu, b0, m2);
                float p21 = __shfl_sync(0xffffffffu, b1, m2);
                float p30 = __shfl_sync(0xffffffffu, b0, m3);
                float p31 = __shfl_sync(0xffffffffu, b1, m3);
                float B0 = sel ? p01 : p00;
                float B1 = sel ? p11 : p10;
                float B2 = sel ? p21 : p20;
                float B3 = sel ? p31 : p30;

                float K0 = fmaf(gi1, B1, gi0 * B0);
                float K1 = fmaf(gi3, B3, gi2 * B2);

                float go00 = __shfl_sync(0xffffffffu, Eo, i_o00);
                float go01 = __shfl_sync(0xffffffffu, Eo, i_o01);
                float go10 = __shfl_sync(0xffffffffu, Eo, i_o10);
                float go11 = __shfl_sync(0xffffffffu, Eo, i_o11);

                b0 = fmaf(go01, K1, go00 * K0);
                b1 = fmaf(go11, K1, go10 * K0);
            }
            b0 *= r; b1 *= r;
        }
    }
}

// ---------------------------------------------------------------------------
// Pass 2: per (batch, 64-step chunk) block of 2 warps. Warp0 recomputes
// alpha, warp1 beta, into fp16 smem; then both warps do 32 LLR t's each.
// ---------------------------------------------------------------------------
__global__ __launch_bounds__(64, 1)
void chunk_kernel(const float* __restrict__ llr_ch, const float* __restrict__ llr_a,
                  float* __restrict__ out) {
    __shared__ __half2 sA[CH][32];
    __shared__ __half2 sBt[CH][32];
    __shared__ float sO[CH];

    const int c = blockIdx.x & (NCHUNK - 1);
    const int b = blockIdx.x >> 5;
    const int tb = c * CH;
    const int w = threadIdx.x >> 5;
    const int L = threadIdx.x & 31;

    const int jj = L & 7;
    const float e0 = (jj & 4) ? -0.5f : 0.5f;
    const float e1 = (jj & 2) ? -0.5f : 0.5f;
    const float eb = (jj & 1) ? -0.5f : 0.5f;

    const float* ch = llr_ch + (size_t)b * (2 * TT);
    const float* la = llr_a + (size_t)b * TT;

    if (w == 0) {
        // ---- alpha chunk (1-step, E-trick) ----
        const int bit = L >> 4;
        const int p0 = (2 * L) & 31, p1 = p0 + 1;
        const int iA = gidx(2 * p0, bit), iB = gidx(2 * p0 + 1, bit);
        const int iC = gidx(2 * p1, bit), iD = gidx(2 * p1 + 1, bit);

        float2 seed = g_fck[b][c][L];
        float a0 = seed.x, a1 = seed.y;

        for (int g = 0; g < CH; g += 4) {
            float S = warp_sum(a0 + a1);
            float r = __fdividef(1.0f, S);

            float E[4], u0[4], u1[4];
#pragma unroll
            for (int k = 0; k < 4; k++) {
                int t = tb + g + k;
                float l0 = __ldg(ch + 2 * t);
                float l1 = __ldg(ch + 2 * t + 1);
                float laa = __ldg(la + t);
                E[k] = __expf(fmaf(e0, l0, fmaf(e1, l1, eb * laa)));
            }
#pragma unroll
            for (int k = 0; k < 4; k++) {
                u0[k] = a0; u1[k] = a1;
                float gA = __shfl_sync(0xffffffffu, E[k], iA);
                float gB = __shfl_sync(0xffffffffu, E[k], iB);
                float gC = __shfl_sync(0xffffffffu, E[k], iC);
                float gD = __shfl_sync(0xffffffffu, E[k], iD);
                float pa0 = __shfl_sync(0xffffffffu, a0, p0);
                float pa1 = __shfl_sync(0xffffffffu, a1, p0);
                float qa0 = __shfl_sync(0xffffffffu, a0, p1);
                float qa1 = __shfl_sync(0xffffffffu, a1, p1);
                a0 = fmaf(gB, pa1, gA * pa0);
                a1 = fmaf(gD, qa1, gC * qa0);
            }
#pragma unroll
            for (int k = 0; k < 4; k++)
                sA[g + k][L] = __floats2half2_rn(fminf(u0[k] * r, 60000.0f),
                                                 fminf(u1[k] * r, 60000.0f));
            a0 *= r; a1 *= r;
        }
    } else {
        // ---- beta chunk (1-step, E-trick) ----
        const int i00 = gidx(2 * L, 0),     i01 = gidx(2 * L, 1);
        const int i10 = gidx(2 * L + 1, 0), i11 = gidx(2 * L + 1, 1);
        const int srcL = L >> 1;
        const int srcH = 16 + (L >> 1);
        const bool odd = (L & 1) != 0;

        float2 seed = g_bck[b][c][L];
        float b0 = seed.x, b1 = seed.y;

        for (int g = CH - 4; g >= 0; g -= 4) {
            float S = warp_sum(b0 + b1);
            float r = __fdividef(1.0f, S);

            float E[4], u0[4], u1[4];
#pragma unroll
            for (int k = 0; k < 4; k++) {
                int t = tb + g + k;
                float l0 = __ldg(ch + 2 * t);
                float l1 = __ldg(ch + 2 * t + 1);
                float laa = __ldg(la + t);
                E[k] = __expf(fmaf(e0, l0, fmaf(e1, l1, eb * laa)));
            }
#pragma unroll
            for (int kk = 0; kk < 4; kk++) {
                int k = 3 - kk;
                u0[k] = b0; u1[k] = b1;   // carry = beta_{t+1} at slot t
                float g00 = __shfl_sync(0xffffffffu, E[k], i00);
                float g01 = __shfl_sync(0xffffffffu, E[k], i01);
                float g10 = __shfl_sync(0xffffffffu, E[k], i10);
                float g11 = __shfl_sync(0xffffffffu, E[k], i11);
                float xb0 = __shfl_sync(0xffffffffu, b0, srcL);
                float xb1 = __shfl_sync(0xffffffffu, b1, srcL);
                float bnL = odd ? xb1 : xb0;
                float yb0 = __shfl_sync(0xffffffffu, b0, srcH);
                float yb1 = __shfl_sync(0xffffffffu, b1, srcH);
                float bnH = odd ? yb1 : yb0;
                b0 = fmaf(g01, bnH, g00 * bnL);
                b1 = fmaf(g11, bnH, g10 * bnL);
            }
#pragma unroll
            for (int k = 0; k < 4; k++)
                sBt[g + k][L] = __floats2half2_rn(fminf(u0[k] * r, 60000.0f),
                                                  fminf(u1[k] * r, 60000.0f));
            b0 *= r; b1 *= r;
        }
    }

    __syncthreads();

    // ---- LLR extraction: 2 warps x 32 t ----
    const int i00 = gidx(2 * L, 0),     i01 = gidx(2 * L, 1);
    const int i10 = gidx(2 * L + 1, 0), i11 = gidx(2 * L + 1, 1);
    const __half* bh = (const __half*)sBt;

#pragma unroll 4
    for (int i = 0; i < 32; i++) {
        int tl = w * 32 + i;
        int t = tb + tl;
        float l0 = __ldg(ch + 2 * t);
        float l1 = __ldg(ch + 2 * t + 1);
        float laa = __ldg(la + t);

        float E = __expf(fmaf(e0, l0, fmaf(e1, l1, eb * laa)));
        float g00 = __shfl_sync(0xffffffffu, E, i00);
        float g01 = __shfl_sync(0xffffffffu, E, i01);
        float g10 = __shfl_sync(0xffffffffu, E, i10);
        float g11 = __shfl_sync(0xffffffffu, E, i11);

        float2 a = __half22float2(sA[tl][L]);
        float bnL = __half2float(bh[tl * 64 + L]);
        float bnH = __half2float(bh[tl * 64 + 32 + L]);

        float J0 = warp_sum(bnL * fmaf(a.y, g10, a.x * g00));
        float J1 = warp_sum(bnH * fmaf(a.y, g11, a.x * g01));
        if (L == 0) sO[tl] = __logf(J0) - __logf(J1);
    }

    __syncthreads();
    if (w == 0) {
        out[(size_t)b * TT + tb + L] = sO[L];
        out[(size_t)b * TT + tb + 32 + L] = sO[32 + L];
    }
}

extern "C" void kernel_launch(void* const* d_in, const int* in_sizes, int n_in,
                              void* d_out, int out_size) {
    const float* llr_ch = (const float*)d_in[0];   // [256, 4096]
    const float* llr_a  = (const float*)d_in[1];   // [256, 2048]
    float* out = (float*)d_out;                    // [256, 2048]

    ckpt_kernel<<<2 * BB, 32>>>(llr_ch, llr_a);
    chunk_kernel<<<BB * NCHUNK, 64>>>(llr_ch, llr_a, out);
}

// round 6
// speedup vs baseline: 3.5261x; 1.2272x over previous
#include <cuda_runtime.h>
#include <cuda_fp16.h>
#include <cstdint>

#define TT 2048
#define BB 256
#define CH 64
#define NCHUNK (TT / CH)   // 32

// Checkpoints: alpha carry at t = c*CH, beta carry (= beta_{(c+1)*CH}).
__device__ float2 g_fck[BB][NCHUNK][32];
__device__ float2 g_bck[BB][NCHUNK][32];

__device__ __forceinline__ float warp_sum(float v) {
#pragma unroll
    for (int o = 16; o; o >>= 1) v += __shfl_xor_sync(0xffffffffu, v, o);
    return v;
}

// sign = 1 - 2*((popc(s&mask) ^ b) & 1)
__device__ __forceinline__ float sg(int s, int mask, int b) {
    return 1.0f - 2.0f * (float)((__popc(s & mask) ^ b) & 1);
}

// ---------------------------------------------------------------------------
// Pass 1: full-length recursions, distance-2 input prefetch, checkpoint
// stores every CH steps. Blocks 0..BB-1: alpha. BB..2BB-1: beta.
// ---------------------------------------------------------------------------
__global__ __launch_bounds__(32, 1)
void ckpt_kernel(const float* __restrict__ llr_ch, const float* __restrict__ llr_a) {
    const int L = threadIdx.x;

    if (blockIdx.x < BB) {
        // ================= forward (alpha) =================================
        const int b = blockIdx.x;
        const float* ch = llr_ch + (size_t)b * (2 * TT);
        const float* la = llr_a + (size_t)b * TT;

        const int bit = L >> 4;
        const int p0 = (2 * L) & 31, p1 = p0 + 1;
        const int sA = 2 * p0;
        const float h0 = 0.5f * sg(sA, 57, bit);
        const float h1 = 0.5f * sg(sA, 27, bit);
        const float hb = 0.5f * (1.0f - 2.0f * (float)bit);

        float a0 = (L == 0) ? 1.0f : 0.0f;
        float a1 = 0.0f;

        // prefetch buffers: P = group t0, Q = group t0+4
        float Pl0[4], Pl1[4], Pla[4], Ql0[4], Ql1[4], Qla[4];
#pragma unroll
        for (int k = 0; k < 4; k++) {
            Pl0[k] = __ldg(ch + 2 * k);     Pl1[k] = __ldg(ch + 2 * k + 1);     Pla[k] = __ldg(la + k);
            Ql0[k] = __ldg(ch + 2 * (4+k)); Ql1[k] = __ldg(ch + 2 * (4+k) + 1); Qla[k] = __ldg(la + 4 + k);
        }

        for (int t0 = 0; t0 < TT; t0 += 8) {
            if ((t0 & (CH - 1)) == 0)
                g_fck[b][t0 >> 6][L] = make_float2(a0, a1);

#pragma unroll 2
            for (int h = 0; h < 2; h++) {
                float S = warp_sum(a0 + a1);
                float r = __fdividef(1.0f, S);

                float l0v[4], l1v[4], lav[4];
#pragma unroll
                for (int k = 0; k < 4; k++) {
                    l0v[k] = h ? Ql0[k] : Pl0[k];
                    l1v[k] = h ? Ql1[k] : Pl1[k];
                    lav[k] = h ? Qla[k] : Pla[k];
                }
                // prefetch group t0+8+4h
#pragma unroll
                for (int k = 0; k < 4; k++) {
                    int tt = t0 + 8 + 4 * h + k;
                    if (tt >= TT) tt = TT - 1;
                    if (h) { Ql0[k] = __ldg(ch + 2 * tt); Ql1[k] = __ldg(ch + 2 * tt + 1); Qla[k] = __ldg(la + tt); }
                    else   { Pl0[k] = __ldg(ch + 2 * tt); Pl1[k] = __ldg(ch + 2 * tt + 1); Pla[k] = __ldg(la + tt); }
                }
#pragma unroll
                for (int k = 0; k < 4; k++) {
                    float U = __expf(h0 * l0v[k]);
                    float V = __expf(h1 * l1v[k]);
                    float W = __expf(hb * lav[k]);
                    float Pg = U * V;
                    float iP = __fdividef(1.0f, Pg);
                    float gC = U * U * iP;
                    float gD = V * V * iP;

                    float pa0 = __shfl_sync(0xffffffffu, a0, p0);
                    float pa1 = __shfl_sync(0xffffffffu, a1, p0);
                    float qa0 = __shfl_sync(0xffffffffu, a0, p1);
                    float qa1 = __shfl_sync(0xffffffffu, a1, p1);

                    a0 = W * fmaf(iP, pa1, Pg * pa0);
                    a1 = W * fmaf(gD, qa1, gC * qa0);
                }
                a0 *= r; a1 *= r;
            }
        }
    } else {
        // ================= backward (beta) =================================
        const int b = blockIdx.x - BB;
        const float* ch = llr_ch + (size_t)b * (2 * TT);
        const float* la = llr_a + (size_t)b * TT;

        const float x0 = 0.5f * sg(2 * L, 57, 0);
        const float x1 = 0.5f * sg(2 * L, 27, 0);
        const int srcL = L >> 1;
        const int srcH = 16 + (L >> 1);
        const bool odd = (L & 1) != 0;

        float b0 = 1.0f / 64.0f, b1 = 1.0f / 64.0f;

        // P = group t0+4 (processed first), Q = group t0
        float Pl0[4], Pl1[4], Pla[4], Ql0[4], Ql1[4], Qla[4];
#pragma unroll
        for (int k = 0; k < 4; k++) {
            int tp = TT - 4 + k, tq = TT - 8 + k;
            Pl0[k] = __ldg(ch + 2 * tp); Pl1[k] = __ldg(ch + 2 * tp + 1); Pla[k] = __ldg(la + tp);
            Ql0[k] = __ldg(ch + 2 * tq); Ql1[k] = __ldg(ch + 2 * tq + 1); Qla[k] = __ldg(la + tq);
        }

        for (int t0 = TT - 8; t0 >= 0; t0 -= 8) {
            if ((t0 & (CH - 1)) == CH - 8)
                g_bck[b][(t0 + 4) >> 6][L] = make_float2(b0, b1);

#pragma unroll 2
            for (int h = 0; h < 2; h++) {
                float S = warp_sum(b0 + b1);
                float r = __fdividef(1.0f, S);

                float l0v[4], l1v[4], lav[4];
#pragma unroll
                for (int k = 0; k < 4; k++) {
                    l0v[k] = h ? Ql0[k] : Pl0[k];
                    l1v[k] = h ? Ql1[k] : Pl1[k];
                    lav[k] = h ? Qla[k] : Pla[k];
                }
                // prefetch group (t0-8+4) for h=0, (t0-8) for h=1
#pragma unroll
                for (int k = 0; k < 4; k++) {
                    int tt = t0 - 8 + 4 * (1 - h) + k;
                    if (tt < 0) tt = 0;
                    if (h) { Ql0[k] = __ldg(ch + 2 * tt); Ql1[k] = __ldg(ch + 2 * tt + 1); Qla[k] = __ldg(la + tt); }
                    else   { Pl0[k] = __ldg(ch + 2 * tt); Pl1[k] = __ldg(ch + 2 * tt + 1); Pla[k] = __ldg(la + tt); }
                }
#pragma unroll
                for (int kk = 0; kk < 4; kk++) {
                    int k = 3 - kk;
                    float X = __expf(fmaf(x0, l0v[k], x1 * l1v[k]));
                    float Y = __expf(0.5f * lav[k]);
                    float Z = X * Y;
                    float iZ = __fdividef(1.0f, Z);
                    float g10 = Y * Y * iZ;
                    float g11 = X * X * iZ;

                    float xb0 = __shfl_sync(0xffffffffu, b0, srcL);
                    float xb1 = __shfl_sync(0xffffffffu, b1, srcL);
                    float bnL = odd ? xb1 : xb0;
                    float yb0 = __shfl_sync(0xffffffffu, b0, srcH);
                    float yb1 = __shfl_sync(0xffffffffu, b1, srcH);
                    float bnH = odd ? yb1 : yb0;

                    b0 = fmaf(iZ, bnH, Z * bnL);
                    b1 = fmaf(g11, bnH, g10 * bnL);
                }
                b0 *= r; b1 *= r;
            }
        }
    }
}

// ---------------------------------------------------------------------------
// Pass 2: per (batch, 64-step chunk) block of 2 warps. Warp0 recomputes
// alpha, warp1 beta, into fp16 smem; then both warps do 32 LLR t's each.
// ---------------------------------------------------------------------------
__global__ __launch_bounds__(64, 1)
void chunk_kernel(const float* __restrict__ llr_ch, const float* __restrict__ llr_a,
                  float* __restrict__ out) {
    __shared__ __half2 sA[CH][32];
    __shared__ __half2 sBt[CH][32];
    __shared__ float sO[CH];

    const int c = blockIdx.x & (NCHUNK - 1);
    const int b = blockIdx.x >> 5;
    const int tb = c * CH;
    const int w = threadIdx.x >> 5;
    const int L = threadIdx.x & 31;

    const float* ch = llr_ch + (size_t)b * (2 * TT);
    const float* la = llr_a + (size_t)b * TT;

    if (w == 0) {
        // ---- alpha chunk ----
        const int bit = L >> 4;
        const int p0 = (2 * L) & 31, p1 = p0 + 1;
        const float h0 = 0.5f * sg(2 * p0, 57, bit);
        const float h1 = 0.5f * sg(2 * p0, 27, bit);
        const float hb = 0.5f * (1.0f - 2.0f * (float)bit);

        float2 seed = g_fck[b][c][L];
        float a0 = seed.x, a1 = seed.y;

        for (int g = 0; g < CH; g += 4) {
            float S = warp_sum(a0 + a1);
            float r = __fdividef(1.0f, S);

            float l0v[4], l1v[4], lav[4], u0[4], u1[4];
#pragma unroll
            for (int k = 0; k < 4; k++) {
                int t = tb + g + k;
                l0v[k] = __ldg(ch + 2 * t);
                l1v[k] = __ldg(ch + 2 * t + 1);
                lav[k] = __ldg(la + t);
            }
#pragma unroll
            for (int k = 0; k < 4; k++) {
                u0[k] = a0; u1[k] = a1;
                float U = __expf(h0 * l0v[k]);
                float V = __expf(h1 * l1v[k]);
                float W = __expf(hb * lav[k]);
                float Pg = U * V;
                float iP = __fdividef(1.0f, Pg);
                float gC = U * U * iP;
                float gD = V * V * iP;

                float pa0 = __shfl_sync(0xffffffffu, a0, p0);
                float pa1 = __shfl_sync(0xffffffffu, a1, p0);
                float qa0 = __shfl_sync(0xffffffffu, a0, p1);
                float qa1 = __shfl_sync(0xffffffffu, a1, p1);

                a0 = W * fmaf(iP, pa1, Pg * pa0);
                a1 = W * fmaf(gD, qa1, gC * qa0);
            }
#pragma unroll
            for (int k = 0; k < 4; k++)
                sA[g + k][L] = __floats2half2_rn(fminf(u0[k] * r, 60000.0f),
                                                 fminf(u1[k] * r, 60000.0f));
            a0 *= r; a1 *= r;
        }
    } else {
        // ---- beta chunk ----
        const float x0 = 0.5f * sg(2 * L, 57, 0);
        const float x1 = 0.5f * sg(2 * L, 27, 0);
        const int srcL = L >> 1;
        const int srcH = 16 + (L >> 1);
        const bool odd = (L & 1) != 0;

        float2 seed = g_bck[b][c][L];
        float b0 = seed.x, b1 = seed.y;

        for (int g = CH - 4; g >= 0; g -= 4) {
            float S = warp_sum(b0 + b1);
            float r = __fdividef(1.0f, S);

            float l0v[4], l1v[4], lav[4], u0[4], u1[4];
#pragma unroll
            for (int k = 0; k < 4; k++) {
                int t = tb + g + k;
                l0v[k] = __ldg(ch + 2 * t);
                l1v[k] = __ldg(ch + 2 * t + 1);
                lav[k] = __ldg(la + t);
            }
#pragma unroll
            for (int kk = 0; kk < 4; kk++) {
                int k = 3 - kk;
                u0[k] = b0; u1[k] = b1;   // carry = beta_{t+1} at slot t
                float X = __expf(fmaf(x0, l0v[k], x1 * l1v[k]));
                float Y = __expf(0.5f * lav[k]);
                float Z = X * Y;
                float iZ = __fdividef(1.0f, Z);
                float g10 = Y * Y * iZ;
                float g11 = X * X * iZ;

                float xb0 = __shfl_sync(0xffffffffu, b0, srcL);
                float xb1 = __shfl_sync(0xffffffffu, b1, srcL);
                float bnL = odd ? xb1 : xb0;
                float yb0 = __shfl_sync(0xffffffffu, b0, srcH);
                float yb1 = __shfl_sync(0xffffffffu, b1, srcH);
                float bnH = odd ? yb1 : yb0;

                b0 = fmaf(iZ, bnH, Z * bnL);
                b1 = fmaf(g11, bnH, g10 * bnL);
            }
#pragma unroll
            for (int k = 0; k < 4; k++)
                sBt[g + k][L] = __floats2half2_rn(fminf(u0[k] * r, 60000.0f),
                                                  fminf(u1[k] * r, 60000.0f));
            b0 *= r; b1 *= r;
        }
    }

    __syncthreads();

    // ---- LLR extraction: 2 warps x 32 t, zero gamma shuffles ----
    const float x0c = 0.5f * sg(2 * L, 57, 0);
    const float x1c = 0.5f * sg(2 * L, 27, 0);
    const __half* bh = (const __half*)sBt;

#pragma unroll 4
    for (int i = 0; i < 32; i++) {
        int tl = w * 32 + i;
        int t = tb + tl;
        float l0 = __ldg(ch + 2 * t);
        float l1 = __ldg(ch + 2 * t + 1);
        float laa = __ldg(la + t);

        float X = __expf(fmaf(x0c, l0, x1c * l1));
        float iX = __fdividef(1.0f, X);

        float2 a = __half22float2(sA[tl][L]);
        float bnL = __half2float(bh[tl * 64 + L]);
        float bnH = __half2float(bh[tl * 64 + 32 + L]);

        // J0 = Y * sum(bnL*(ax*X + ay/X)),  J1 = (1/Y) * sum(bnH*(ax/X + ay*X))
        // llr = log J0 - log J1 = la + log(S0) - log(S1)
        float S0 = warp_sum(bnL * fmaf(a.y, iX, a.x * X));
        float S1 = warp_sum(bnH * fmaf(a.y, X, a.x * iX));
        if (L == 0) sO[tl] = laa + __logf(S0) - __logf(S1);
    }

    __syncthreads();
    if (w == 0) {
        out[(size_t)b * TT + tb + L] = sO[L];
        out[(size_t)b * TT + tb + 32 + L] = sO[32 + L];
    }
}

extern "C" void kernel_launch(void* const* d_in, const int* in_sizes, int n_in,
                              void* d_out, int out_size) {
    const float* llr_ch = (const float*)d_in[0];   // [256, 4096]
    const float* llr_a  = (const float*)d_in[1];   // [256, 2048]
    float* out = (float*)d_out;                    // [256, 2048]

    ckpt_kernel<<<2 * BB, 32>>>(llr_ch, llr_a);
    chunk_kernel<<<BB * NCHUNK, 64>>>(llr_ch, llr_a, out);
}

// round 7
// speedup vs baseline: 4.4706x; 1.2679x over previous
#include <cuda_runtime.h>
#include <cuda_fp16.h>
#include <cstdint>

#define TT 2048
#define BB 256
#define CH 64
#define NCHUNK (TT / CH)   // 32

// Checkpoints. fck: lane L holds (alpha[2L], alpha[2L+1]).
//              bck: lane L holds (beta[L], beta[L+32])   <-- stride-32 layout
__device__ float2 g_fck[BB][NCHUNK][32];
__device__ float2 g_bck[BB][NCHUNK][32];

// Warp-uniform max of positive floats via integer redux (f32 redux not on sm_103).
__device__ __forceinline__ float warp_max_pos(float v) {
    unsigned r;
    asm volatile("redux.sync.max.u32 %0, %1, 0xffffffff;"
                 : "=r"(r) : "r"(__float_as_uint(v)));
    return __uint_as_float(r);
}

// sign = 1 - 2*((popc(s&mask) ^ b) & 1)
__device__ __forceinline__ float sg(int s, int mask, int b) {
    return 1.0f - 2.0f * (float)((__popc(s & mask) ^ b) & 1);
}

// ---------------------------------------------------------------------------
// Pass 1: full-length recursions; distance-2 prefetch; redux-max deferred
// normalization (folded into next group's gamma coefficients).
// Blocks 0..BB-1: alpha. BB..2BB-1: beta.
// ---------------------------------------------------------------------------
__global__ __launch_bounds__(32, 1)
void ckpt_kernel(const float* __restrict__ llr_ch, const float* __restrict__ llr_a) {
    const int L = threadIdx.x;

    if (blockIdx.x < BB) {
        // ================= forward (alpha) =================================
        const int b = blockIdx.x;
        const float* ch = llr_ch + (size_t)b * (2 * TT);
        const float* la = llr_a + (size_t)b * TT;

        const int bit = L >> 4;
        const int p0 = (2 * L) & 31, p1 = p0 + 1;
        const float h0 = 0.5f * sg(2 * p0, 57, bit);
        const float h1 = 0.5f * sg(2 * p0, 27, bit);
        const float hb = 0.5f * (1.0f - 2.0f * (float)bit);

        float a0 = (L == 0) ? 1.0f : 0.0f;
        float a1 = 0.0f;
        float rq = 1.0f;   // pending normalization, applied in next group's step 0

        float Pl0[4], Pl1[4], Pla[4], Ql0[4], Ql1[4], Qla[4];
#pragma unroll
        for (int k = 0; k < 4; k++) {
            Pl0[k] = __ldg(ch + 2 * k);     Pl1[k] = __ldg(ch + 2 * k + 1);     Pla[k] = __ldg(la + k);
            Ql0[k] = __ldg(ch + 2 * (4+k)); Ql1[k] = __ldg(ch + 2 * (4+k) + 1); Qla[k] = __ldg(la + 4 + k);
        }

        for (int t0 = 0; t0 < TT; t0 += 8) {
            if ((t0 & (CH - 1)) == 0)
                g_fck[b][t0 >> 6][L] = make_float2(a0, a1);

#pragma unroll 2
            for (int h = 0; h < 2; h++) {
                float m = warp_max_pos(a0 + a1);

                float l0v[4], l1v[4], lav[4];
#pragma unroll
                for (int k = 0; k < 4; k++) {
                    l0v[k] = h ? Ql0[k] : Pl0[k];
                    l1v[k] = h ? Ql1[k] : Pl1[k];
                    lav[k] = h ? Qla[k] : Pla[k];
                }
#pragma unroll
                for (int k = 0; k < 4; k++) {
                    int tt = t0 + 8 + 4 * h + k;
                    if (tt >= TT) tt = TT - 1;
                    if (h) { Ql0[k] = __ldg(ch + 2 * tt); Ql1[k] = __ldg(ch + 2 * tt + 1); Qla[k] = __ldg(la + tt); }
                    else   { Pl0[k] = __ldg(ch + 2 * tt); Pl1[k] = __ldg(ch + 2 * tt + 1); Pla[k] = __ldg(la + tt); }
                }
#pragma unroll
                for (int k = 0; k < 4; k++) {
                    float U = __expf(h0 * l0v[k]);
                    float V = __expf(h1 * l1v[k]);
                    float W = __expf(hb * lav[k]);
                    if (k == 0) W *= rq;          // deferred normalization
                    float Pg = U * V;
                    float iP = __fdividef(1.0f, Pg);
                    float WiP = W * iP;
                    float A1 = Pg * W;
                    float A3 = U * U * WiP;
                    float A4 = V * V * WiP;

                    float pa0 = __shfl_sync(0xffffffffu, a0, p0);
                    float pa1 = __shfl_sync(0xffffffffu, a1, p0);
                    float qa0 = __shfl_sync(0xffffffffu, a0, p1);
                    float qa1 = __shfl_sync(0xffffffffu, a1, p1);

                    a0 = fmaf(WiP, pa1, A1 * pa0);
                    a1 = fmaf(A4, qa1, A3 * qa0);
                }
                rq = __fdividef(1.0f, m);
            }
        }
    } else {
        // ================= backward (beta), stride-32 layout ================
        const int b = blockIdx.x - BB;
        const float* ch = llr_ch + (size_t)b * (2 * TT);
        const float* la = llr_a + (size_t)b * TT;

        const float x0L = 0.5f * sg(L, 57, 0);
        const float x1L = 0.5f * sg(L, 27, 0);
        const float tx0 = 2.0f * x0L;
        const int srcA = L >> 1;
        const int srcB = 16 + (L >> 1);

        float b0 = 1.0f / 64.0f, b1 = 1.0f / 64.0f;   // beta[L], beta[L+32]
        float rq = 1.0f;

        float Pl0[4], Pl1[4], Pla[4], Ql0[4], Ql1[4], Qla[4];
#pragma unroll
        for (int k = 0; k < 4; k++) {
            int tp = TT - 4 + k, tq = TT - 8 + k;
            Pl0[k] = __ldg(ch + 2 * tp); Pl1[k] = __ldg(ch + 2 * tp + 1); Pla[k] = __ldg(la + tp);
            Ql0[k] = __ldg(ch + 2 * tq); Ql1[k] = __ldg(ch + 2 * tq + 1); Qla[k] = __ldg(la + tq);
        }

        for (int t0 = TT - 8; t0 >= 0; t0 -= 8) {
            if ((t0 & (CH - 1)) == CH - 8)
                g_bck[b][(t0 + 4) >> 6][L] = make_float2(b0, b1);

#pragma unroll 2
            for (int h = 0; h < 2; h++) {
                float m = warp_max_pos(b0 + b1);

                float l0v[4], l1v[4], lav[4];
#pragma unroll
                for (int k = 0; k < 4; k++) {
                    l0v[k] = h ? Ql0[k] : Pl0[k];
                    l1v[k] = h ? Ql1[k] : Pl1[k];
                    lav[k] = h ? Qla[k] : Pla[k];
                }
#pragma unroll
                for (int k = 0; k < 4; k++) {
                    int tt = t0 - 8 + 4 * (1 - h) + k;
                    if (tt < 0) tt = 0;
                    if (h) { Ql0[k] = __ldg(ch + 2 * tt); Ql1[k] = __ldg(ch + 2 * tt + 1); Qla[k] = __ldg(la + tt); }
                    else   { Pl0[k] = __ldg(ch + 2 * tt); Pl1[k] = __ldg(ch + 2 * tt + 1); Pla[k] = __ldg(la + tt); }
                }
#pragma unroll
                for (int kk = 0; kk < 4; kk++) {
                    int k = 3 - kk;
                    float Z = __expf(fmaf(x0L, l0v[k], fmaf(x1L, l1v[k], 0.5f * lav[k])));
                    float F = __expf(tx0 * l0v[k]);
                    if (kk == 0) Z *= rq;
                    float iZ = __fdividef(1.0f, Z);
                    float iF = __fdividef(1.0f, F);
                    if (kk == 0) iZ = iZ * rq * rq;   // iZ of scaled Z, rescaled: (rq/Z)... keep coeff scale uniform
                    // NOTE: after "Z *= rq", 1/Z already carries 1/rq; multiply by rq^2 to get rq*iZ_orig
                    float c10 = Z * iF;
                    float c11 = iZ * F;

                    float s0 = __shfl_sync(0xffffffffu, b0, srcA);
                    float s1 = __shfl_sync(0xffffffffu, b1, srcA);
                    float t0s = __shfl_sync(0xffffffffu, b0, srcB);
                    float t1s = __shfl_sync(0xffffffffu, b1, srcB);

                    b0 = fmaf(iZ, s1, Z * s0);
                    b1 = fmaf(c11, t1s, c10 * t0s);
                }
                rq = __fdividef(1.0f, m);
            }
        }
    }
}

// ---------------------------------------------------------------------------
// Pass 2: (batch, 64-step chunk) blocks of 2 warps. Warp0 recomputes alpha,
// warp1 beta, into fp16 smem transposed [state][t] (65-word row stride,
// conflict-free both directions); then lane-per-t LLR with no shuffles.
// ---------------------------------------------------------------------------
__global__ __launch_bounds__(64, 1)
void chunk_kernel(const float* __restrict__ llr_ch, const float* __restrict__ llr_a,
                  float* __restrict__ out) {
    __shared__ __half2 sA[32][CH + 1];
    __shared__ __half2 sB[32][CH + 1];

    const int c = blockIdx.x & (NCHUNK - 1);
    const int b = blockIdx.x >> 5;
    const int tb = c * CH;
    const int w = threadIdx.x >> 5;
    const int L = threadIdx.x & 31;

    const float* ch = llr_ch + (size_t)b * (2 * TT);
    const float* la = llr_a + (size_t)b * TT;

    if (w == 0) {
        // ---- alpha chunk ----
        const int bit = L >> 4;
        const int p0 = (2 * L) & 31, p1 = p0 + 1;
        const float h0 = 0.5f * sg(2 * p0, 57, bit);
        const float h1 = 0.5f * sg(2 * p0, 27, bit);
        const float hb = 0.5f * (1.0f - 2.0f * (float)bit);

        float2 seed = g_fck[b][c][L];
        float a0 = seed.x, a1 = seed.y;

        for (int g = 0; g < CH; g += 4) {
            float r = __fdividef(1.0f, warp_max_pos(a0 + a1));

            float l0v[4], l1v[4], lav[4], u0[4], u1[4];
#pragma unroll
            for (int k = 0; k < 4; k++) {
                int t = tb + g + k;
                l0v[k] = __ldg(ch + 2 * t);
                l1v[k] = __ldg(ch + 2 * t + 1);
                lav[k] = __ldg(la + t);
            }
#pragma unroll
            for (int k = 0; k < 4; k++) {
                u0[k] = a0; u1[k] = a1;
                float U = __expf(h0 * l0v[k]);
                float V = __expf(h1 * l1v[k]);
                float W = __expf(hb * lav[k]);
                float Pg = U * V;
                float iP = __fdividef(1.0f, Pg);
                float WiP = W * iP;
                float A1 = Pg * W;
                float A3 = U * U * WiP;
                float A4 = V * V * WiP;

                float pa0 = __shfl_sync(0xffffffffu, a0, p0);
                float pa1 = __shfl_sync(0xffffffffu, a1, p0);
                float qa0 = __shfl_sync(0xffffffffu, a0, p1);
                float qa1 = __shfl_sync(0xffffffffu, a1, p1);

                a0 = fmaf(WiP, pa1, A1 * pa0);
                a1 = fmaf(A4, qa1, A3 * qa0);
            }
#pragma unroll
            for (int k = 0; k < 4; k++)
                sA[L][g + k] = __floats2half2_rn(fminf(u0[k] * r, 60000.0f),
                                                 fminf(u1[k] * r, 60000.0f));
            a0 *= r; a1 *= r;
        }
    } else {
        // ---- beta chunk, stride-32 layout ----
        const float x0L = 0.5f * sg(L, 57, 0);
        const float x1L = 0.5f * sg(L, 27, 0);
        const float tx0 = 2.0f * x0L;
        const int srcA = L >> 1;
        const int srcB = 16 + (L >> 1);

        float2 seed = g_bck[b][c][L];
        float b0 = seed.x, b1 = seed.y;

        for (int g = CH - 4; g >= 0; g -= 4) {
            float r = __fdividef(1.0f, warp_max_pos(b0 + b1));

            float l0v[4], l1v[4], lav[4], u0[4], u1[4];
#pragma unroll
            for (int k = 0; k < 4; k++) {
                int t = tb + g + k;
                l0v[k] = __ldg(ch + 2 * t);
                l1v[k] = __ldg(ch + 2 * t + 1);
                lav[k] = __ldg(la + t);
            }
#pragma unroll
            for (int kk = 0; kk < 4; kk++) {
                int k = 3 - kk;
                u0[k] = b0; u1[k] = b1;   // carry = beta_{t+1}[L], beta_{t+1}[L+32]
                float Z = __expf(fmaf(x0L, l0v[k], fmaf(x1L, l1v[k], 0.5f * lav[k])));
                float F = __expf(tx0 * l0v[k]);
                float iZ = __fdividef(1.0f, Z);
                float iF = __fdividef(1.0f, F);
                float c10 = Z * iF;
                float c11 = iZ * F;

                float s0 = __shfl_sync(0xffffffffu, b0, srcA);
                float s1 = __shfl_sync(0xffffffffu, b1, srcA);
                float t0s = __shfl_sync(0xffffffffu, b0, srcB);
                float t1s = __shfl_sync(0xffffffffu, b1, srcB);

                b0 = fmaf(iZ, s1, Z * s0);
                b1 = fmaf(c11, t1s, c10 * t0s);
            }
#pragma unroll
            for (int k = 0; k < 4; k++)
                sB[L][g + k] = __floats2half2_rn(fminf(u0[k] * r, 60000.0f),
                                                 fminf(u1[k] * r, 60000.0f));
            b0 *= r; b1 *= r;
        }
    }

    __syncthreads();

    // ---- LLR: lane-per-t, no shuffles, no reductions ----
    {
        int tl = w * 32 + L;
        int t = tb + tl;
        float l0 = __ldg(ch + 2 * t);
        float l1 = __ldg(ch + 2 * t + 1);
        float laa = __ldg(la + t);

        float P = __expf(0.5f * (l0 + l1));
        float Q = __expf(0.5f * (l0 - l1));
        float iPv = __fdividef(1.0f, P);
        float iQv = __fdividef(1.0f, Q);

        float S0 = 0.0f, S1 = 0.0f;
#pragma unroll
        for (int s = 0; s < 32; s++) {
            const int par0 = (__popc(s & 28)) & 1;   // sign of l0 term for state 2s
            const int par1 = (__popc(s & 13)) & 1;   // sign of l1 term for state 2s
            float X  = par0 ? (par1 ? iPv : iQv) : (par1 ? Q : P);
            float iX = par0 ? (par1 ? P : Q) : (par1 ? iQv : iPv);

            float2 a  = __half22float2(sA[s][tl]);
            float2 bb = __half22float2(sB[s][tl]);
            S0 = fmaf(bb.x, fmaf(a.y, iX, a.x * X), S0);
            S1 = fmaf(bb.y, fmaf(a.y, X, a.x * iX), S1);
        }
        out[(size_t)b * TT + t] = laa + __logf(S0) - __logf(S1);
    }
}

extern "C" void kernel_launch(void* const* d_in, const int* in_sizes, int n_in,
                              void* d_out, int out_size) {
    const float* llr_ch = (const float*)d_in[0];   // [256, 4096]
    const float* llr_a  = (const float*)d_in[1];   // [256, 2048]
    float* out = (float*)d_out;                    // [256, 2048]

    ckpt_kernel<<<2 * BB, 32>>>(llr_ch, llr_a);
    chunk_kernel<<<BB * NCHUNK, 64>>>(llr_ch, llr_a, out);
}

// round 8
// speedup vs baseline: 7.2375x; 1.6189x over previous
#include <cuda_runtime.h>
#include <cuda_fp16.h>
#include <cstdint>

#define TT 2048
#define BB 256
#define CH 128
#define WU 64
#define NCHUNK (TT / CH)   // 16

// Warp-uniform max of positive floats via integer redux (f32 redux not on sm_103).
__device__ __forceinline__ float warp_max_pos(float v) {
    unsigned r;
    asm volatile("redux.sync.max.u32 %0, %1, 0xffffffff;"
                 : "=r"(r) : "r"(__float_as_uint(v)));
    return __uint_as_float(r);
}

// sign = 1 - 2*((popc(s&mask) ^ b) & 1)
__device__ __forceinline__ float sg(int s, int mask, int b) {
    return 1.0f - 2.0f * (float)((__popc(s & mask) ^ b) & 1);
}

// ---------------------------------------------------------------------------
// Single fused kernel: one block per (batch, 128-step chunk), 2 warps.
// Warp0: alpha recursion, warmed up from a uniform seed WU steps before the
//        chunk (exact delta seed for chunk 0).
// Warp1: beta recursion, warmed up from uniform WU steps after the chunk
//        (exact — beta_T is uniform — for the last chunk).
// Both write fp16 values into transposed smem [state][t] (stride CH+1,
// conflict-free both directions), then each warp does 64 lane-per-t LLRs.
// ---------------------------------------------------------------------------
__global__ __launch_bounds__(64, 1)
void bcjr_kernel(const float* __restrict__ llr_ch, const float* __restrict__ llr_a,
                 float* __restrict__ out) {
    __shared__ __half2 sA[32][CH + 1];
    __shared__ __half2 sB[32][CH + 1];

    const int c = blockIdx.x & (NCHUNK - 1);
    const int b = blockIdx.x >> 4;           // NCHUNK = 16
    const int tb = c * CH;
    const int w = threadIdx.x >> 5;
    const int L = threadIdx.x & 31;

    const float* ch = llr_ch + (size_t)b * (2 * TT);
    const float* la = llr_a + (size_t)b * TT;

    if (w == 0) {
        // ---- alpha: warmup + chunk ----
        const int bit = L >> 4;
        const int p0 = (2 * L) & 31, p1 = p0 + 1;
        const float h0 = 0.5f * sg(2 * p0, 57, bit);
        const float h1 = 0.5f * sg(2 * p0, 27, bit);
        const float hb = 0.5f * (1.0f - 2.0f * (float)bit);

        float a0, a1;
        int gs;
        if (c == 0) { a0 = (L == 0) ? 1.0f : 0.0f; a1 = 0.0f; gs = 0; }
        else        { a0 = 1.0f / 64.0f; a1 = 1.0f / 64.0f;   gs = -WU; }

        for (int g = gs; g < CH; g += 4) {
            float r = __fdividef(1.0f, warp_max_pos(a0 + a1));

            float l0v[4], l1v[4], lav[4], u0[4], u1[4];
#pragma unroll
            for (int k = 0; k < 4; k++) {
                int t = tb + g + k;
                l0v[k] = __ldg(ch + 2 * t);
                l1v[k] = __ldg(ch + 2 * t + 1);
                lav[k] = __ldg(la + t);
            }
#pragma unroll
            for (int k = 0; k < 4; k++) {
                u0[k] = a0; u1[k] = a1;
                float U = __expf(h0 * l0v[k]);
                float V = __expf(h1 * l1v[k]);
                float Wf = __expf(hb * lav[k]);
                float Pg = U * V;
                float iP = __fdividef(1.0f, Pg);
                float WiP = Wf * iP;
                float A1 = Pg * Wf;
                float A3 = U * U * WiP;
                float A4 = V * V * WiP;

                float pa0 = __shfl_sync(0xffffffffu, a0, p0);
                float pa1 = __shfl_sync(0xffffffffu, a1, p0);
                float qa0 = __shfl_sync(0xffffffffu, a0, p1);
                float qa1 = __shfl_sync(0xffffffffu, a1, p1);

                a0 = fmaf(WiP, pa1, A1 * pa0);
                a1 = fmaf(A4, qa1, A3 * qa0);
            }
            if (g >= 0) {
#pragma unroll
                for (int k = 0; k < 4; k++)
                    sA[L][g + k] = __floats2half2_rn(fminf(u0[k] * r, 60000.0f),
                                                     fminf(u1[k] * r, 60000.0f));
            }
            a0 *= r; a1 *= r;
        }
    } else {
        // ---- beta: warmup + chunk (stride-32 layout: lane L = beta[L], beta[L+32]) ----
        const float x0L = 0.5f * sg(L, 57, 0);
        const float x1L = 0.5f * sg(L, 27, 0);
        const float tx0 = 2.0f * x0L;
        const int srcA = L >> 1;
        const int srcB = 16 + (L >> 1);

        float b0 = 1.0f / 64.0f, b1 = 1.0f / 64.0f;
        const int ge = (c == NCHUNK - 1) ? CH : CH + WU;

        for (int g = ge - 4; g >= 0; g -= 4) {
            float r = __fdividef(1.0f, warp_max_pos(b0 + b1));

            float l0v[4], l1v[4], lav[4], u0[4], u1[4];
#pragma unroll
            for (int k = 0; k < 4; k++) {
                int t = tb + g + k;
                l0v[k] = __ldg(ch + 2 * t);
                l1v[k] = __ldg(ch + 2 * t + 1);
                lav[k] = __ldg(la + t);
            }
#pragma unroll
            for (int kk = 0; kk < 4; kk++) {
                int k = 3 - kk;
                u0[k] = b0; u1[k] = b1;   // carry = beta_{t+1}[L], beta_{t+1}[L+32]
                float Z = __expf(fmaf(x0L, l0v[k], fmaf(x1L, l1v[k], 0.5f * lav[k])));
                float F = __expf(tx0 * l0v[k]);
                float iZ = __fdividef(1.0f, Z);
                float iF = __fdividef(1.0f, F);
                float c10 = Z * iF;
                float c11 = iZ * F;

                float s0 = __shfl_sync(0xffffffffu, b0, srcA);
                float s1 = __shfl_sync(0xffffffffu, b1, srcA);
                float t0s = __shfl_sync(0xffffffffu, b0, srcB);
                float t1s = __shfl_sync(0xffffffffu, b1, srcB);

                b0 = fmaf(iZ, s1, Z * s0);
                b1 = fmaf(c11, t1s, c10 * t0s);
            }
            if (g < CH) {
#pragma unroll
                for (int k = 0; k < 4; k++)
                    sB[L][g + k] = __floats2half2_rn(fminf(u0[k] * r, 60000.0f),
                                                     fminf(u1[k] * r, 60000.0f));
            }
            b0 *= r; b1 *= r;
        }
    }

    __syncthreads();

    // ---- LLR: lane-per-t, no shuffles, no reductions; 64 t per warp ----
    for (int pass = 0; pass < 2; pass++) {
        int tl = w * 64 + pass * 32 + L;
        int t = tb + tl;
        float l0 = __ldg(ch + 2 * t);
        float l1 = __ldg(ch + 2 * t + 1);
        float laa = __ldg(la + t);

        float P = __expf(0.5f * (l0 + l1));
        float Q = __expf(0.5f * (l0 - l1));
        float iPv = __fdividef(1.0f, P);
        float iQv = __fdividef(1.0f, Q);

        float S0 = 0.0f, S1 = 0.0f;
#pragma unroll
        for (int s = 0; s < 32; s++) {
            const int par0 = (__popc(s & 28)) & 1;   // sign of l0 term for state 2s
            const int par1 = (__popc(s & 13)) & 1;   // sign of l1 term for state 2s
            float X  = par0 ? (par1 ? iPv : iQv) : (par1 ? Q : P);
            float iX = par0 ? (par1 ? P : Q) : (par1 ? iQv : iPv);

            float2 a  = __half22float2(sA[s][tl]);
            float2 bb = __half22float2(sB[s][tl]);
            S0 = fmaf(bb.x, fmaf(a.y, iX, a.x * X), S0);
            S1 = fmaf(bb.y, fmaf(a.y, X, a.x * iX), S1);
        }
        out[(size_t)b * TT + t] = laa + __logf(S0) - __logf(S1);
    }
}

extern "C" void kernel_launch(void* const* d_in, const int* in_sizes, int n_in,
                              void* d_out, int out_size) {
    const float* llr_ch = (const float*)d_in[0];   // [256, 4096]
    const float* llr_a  = (const float*)d_in[1];   // [256, 2048]
    float* out = (float*)d_out;                    // [256, 2048]

    bcjr_kernel<<<BB * NCHUNK, 64>>>(llr_ch, llr_a, out);
}

// round 9
// speedup vs baseline: 8.9329x; 1.2342x over previous
#include <cuda_runtime.h>
#include <cuda_fp16.h>
#include <cstdint>

#define TT 2048
#define BB 256
#define CH 64
#define WU 32
#define NCHUNK (TT / CH)   // 32

// Warp-uniform max of positive floats via integer redux (f32 redux not on sm_103).
__device__ __forceinline__ float warp_max_pos(float v) {
    unsigned r;
    asm volatile("redux.sync.max.u32 %0, %1, 0xffffffff;"
                 : "=r"(r) : "r"(__float_as_uint(v)));
    return __uint_as_float(r);
}

// sign = 1 - 2*((popc(s&mask) ^ b) & 1)
__device__ __forceinline__ float sg(int s, int mask, int b) {
    return 1.0f - 2.0f * (float)((__popc(s & mask) ^ b) & 1);
}

// ---------------------------------------------------------------------------
// One block per (batch, 64-step chunk), 2 warps.
// Warp0: alpha recursion, warmed up from a uniform seed WU steps before the
//        chunk (exact delta seed for chunk 0).
// Warp1: beta recursion, warmed up from uniform WU steps after the chunk
//        (exact for the last chunk — beta_T is uniform).
// fp16 smem transposed [state][t] (stride CH+1), then lane-per-t LLR.
// ---------------------------------------------------------------------------
__global__ __launch_bounds__(64, 1)
void bcjr_kernel(const float* __restrict__ llr_ch, const float* __restrict__ llr_a,
                 float* __restrict__ out) {
    __shared__ __half2 sA[32][CH + 1];
    __shared__ __half2 sB[32][CH + 1];

    const int c = blockIdx.x & (NCHUNK - 1);
    const int b = blockIdx.x >> 5;           // NCHUNK = 32
    const int tb = c * CH;
    const int w = threadIdx.x >> 5;
    const int L = threadIdx.x & 31;

    const float* ch = llr_ch + (size_t)b * (2 * TT);
    const float2* ch2 = (const float2*)ch;
    const float* la = llr_a + (size_t)b * TT;

    if (w == 0) {
        // ---- alpha: warmup + chunk ----
        const int bit = L >> 4;
        const int p0 = (2 * L) & 31, p1 = p0 + 1;
        const float h0 = 0.5f * sg(2 * p0, 57, bit);
        const float h1 = 0.5f * sg(2 * p0, 27, bit);
        const float hb = 0.5f * (1.0f - 2.0f * (float)bit);

        float a0, a1;
        int gs;
        if (c == 0) { a0 = (L == 0) ? 1.0f : 0.0f; a1 = 0.0f; gs = 0; }
        else        { a0 = 1.0f / 64.0f; a1 = 1.0f / 64.0f;   gs = -WU; }

        for (int g = gs; g < CH; g += 4) {
            float r = __fdividef(1.0f, warp_max_pos(a0 + a1));

            float l0v[4], l1v[4], lav[4], u0[4], u1[4];
#pragma unroll
            for (int k = 0; k < 4; k++) {
                int t = tb + g + k;
                float2 l01 = __ldg(ch2 + t);
                l0v[k] = l01.x; l1v[k] = l01.y;
                lav[k] = __ldg(la + t);
            }
#pragma unroll
            for (int k = 0; k < 4; k++) {
                u0[k] = a0; u1[k] = a1;
                float x = h0 * l0v[k];
                float y = h1 * l1v[k];
                float z = hb * lav[k];
                float spy = x + y, dmy = x - y;
                float A1 = __expf(z + spy);   // gamma(2p0,   bit)
                float A2 = __expf(z - spy);   // gamma(2p0+1, bit)
                float A3 = __expf(z + dmy);   // gamma(2p1,   bit)
                float A4 = __expf(z - dmy);   // gamma(2p1+1, bit)

                float pa0 = __shfl_sync(0xffffffffu, a0, p0);
                float pa1 = __shfl_sync(0xffffffffu, a1, p0);
                float qa0 = __shfl_sync(0xffffffffu, a0, p1);
                float qa1 = __shfl_sync(0xffffffffu, a1, p1);

                a0 = fmaf(A2, pa1, A1 * pa0);
                a1 = fmaf(A4, qa1, A3 * qa0);
            }
            if (g >= 0) {
#pragma unroll
                for (int k = 0; k < 4; k++)
                    sA[L][g + k] = __floats2half2_rn(fminf(u0[k] * r, 60000.0f),
                                                     fminf(u1[k] * r, 60000.0f));
            }
            a0 *= r; a1 *= r;
        }
    } else {
        // ---- beta: warmup + chunk (stride-32 layout: lane L = beta[L], beta[L+32]) ----
        const float x0L = 0.5f * sg(L, 57, 0);
        const float x1L = 0.5f * sg(L, 27, 0);
        const int srcA = L >> 1;
        const int srcB = 16 + (L >> 1);

        float b0 = 1.0f / 64.0f, b1 = 1.0f / 64.0f;
        const int ge = (c == NCHUNK - 1) ? CH : CH + WU;

        for (int g = ge - 4; g >= 0; g -= 4) {
            float r = __fdividef(1.0f, warp_max_pos(b0 + b1));

            float l0v[4], l1v[4], lav[4], u0[4], u1[4];
#pragma unroll
            for (int k = 0; k < 4; k++) {
                int t = tb + g + k;
                float2 l01 = __ldg(ch2 + t);
                l0v[k] = l01.x; l1v[k] = l01.y;
                lav[k] = __ldg(la + t);
            }
#pragma unroll
            for (int kk = 0; kk < 4; kk++) {
                int k = 3 - kk;
                u0[k] = b0; u1[k] = b1;   // carry = beta_{t+1}[L], beta_{t+1}[L+32]
                float a = x0L * l0v[k];
                float b2 = fmaf(x1L, l1v[k], 0.5f * lav[k]);
                float sm = a + b2, df = a - b2;
                float Z   = __expf(sm);    // gamma(L, 0)
                float iZ  = __expf(-sm);   // gamma(L, 1)
                float c10 = __expf(-df);   // gamma(L+32, 0)
                float c11 = __expf(df);    // gamma(L+32, 1)

                float s0 = __shfl_sync(0xffffffffu, b0, srcA);
                float s1 = __shfl_sync(0xffffffffu, b1, srcA);
                float t0s = __shfl_sync(0xffffffffu, b0, srcB);
                float t1s = __shfl_sync(0xffffffffu, b1, srcB);

                b0 = fmaf(iZ, s1, Z * s0);
                b1 = fmaf(c11, t1s, c10 * t0s);
            }
            if (g < CH) {
#pragma unroll
                for (int k = 0; k < 4; k++)
                    sB[L][g + k] = __floats2half2_rn(fminf(u0[k] * r, 60000.0f),
                                                     fminf(u1[k] * r, 60000.0f));
            }
            b0 *= r; b1 *= r;
        }
    }

    __syncthreads();

    // ---- LLR: lane-per-t, no shuffles, no reductions; 32 t per warp ----
    {
        int tl = w * 32 + L;
        int t = tb + tl;
        float2 l01 = __ldg(ch2 + t);
        float l0 = l01.x, l1 = l01.y;
        float laa = __ldg(la + t);

        float P = __expf(0.5f * (l0 + l1));
        float Q = __expf(0.5f * (l0 - l1));
        float iPv = __fdividef(1.0f, P);
        float iQv = __fdividef(1.0f, Q);

        float S0 = 0.0f, S1 = 0.0f;
#pragma unroll
        for (int s = 0; s < 32; s++) {
            const int par0 = (__popc(s & 28)) & 1;   // sign of l0 term for state 2s
            const int par1 = (__popc(s & 13)) & 1;   // sign of l1 term for state 2s
            float X  = par0 ? (par1 ? iPv : iQv) : (par1 ? Q : P);
            float iX = par0 ? (par1 ? P : Q) : (par1 ? iQv : iPv);

            float2 a  = __half22float2(sA[s][tl]);
            float2 bb = __half22float2(sB[s][tl]);
            S0 = fmaf(bb.x, fmaf(a.y, iX, a.x * X), S0);
            S1 = fmaf(bb.y, fmaf(a.y, X, a.x * iX), S1);
        }
        out[(size_t)b * TT + t] = laa + __logf(S0) - __logf(S1);
    }
}

extern "C" void kernel_launch(void* const* d_in, const int* in_sizes, int n_in,
                              void* d_out, int out_size) {
    const float* llr_ch = (const float*)d_in[0];   // [256, 4096]
    const float* llr_a  = (const float*)d_in[1];   // [256, 2048]
    float* out = (float*)d_out;                    // [256, 2048]

    bcjr_kernel<<<BB * NCHUNK, 64>>>(llr_ch, llr_a, out);
}

// round 10
// speedup vs baseline: 10.1692x; 1.1384x over previous
#include <cuda_runtime.h>
#include <cuda_fp16.h>
#include <cstdint>

#define TT 2048
#define BB 256
#define CH 64
#define WU 32
#define NCHUNK (TT / CH)   // 32

#define LOG2E 1.4426950408889634f
#define LN2   0.6931471805599453f

// Warp-uniform max of positive floats via integer redux (f32 redux not on sm_103).
__device__ __forceinline__ float warp_max_pos(float v) {
    unsigned r;
    asm volatile("redux.sync.max.u32 %0, %1, 0xffffffff;"
                 : "=r"(r) : "r"(__float_as_uint(v)));
    return __uint_as_float(r);
}

__device__ __forceinline__ float ex2(float x) {
    float y; asm("ex2.approx.f32 %0, %1;" : "=f"(y) : "f"(x)); return y;
}
__device__ __forceinline__ float lg2(float x) {
    float y; asm("lg2.approx.f32 %0, %1;" : "=f"(y) : "f"(x)); return y;
}

// sign = 1 - 2*((popc(s&mask) ^ b) & 1)
__device__ __forceinline__ float sg(int s, int mask, int b) {
    return 1.0f - 2.0f * (float)((__popc(s & mask) ^ b) & 1);
}

// ---------------------------------------------------------------------------
// One block per (batch, 64-step chunk), 2 warps.
// Warp0: alpha recursion (uniform seed WU steps early; exact delta for c=0).
// Warp1: beta recursion (uniform seed WU steps late; exact for last chunk).
// fp16 smem transposed [state][t] (stride CH+1), then lane-per-t LLR.
// All exp coefficients pre-scaled by log2(e); raw ex2.approx.
// ---------------------------------------------------------------------------
__global__ __launch_bounds__(64, 1)
void bcjr_kernel(const float* __restrict__ llr_ch, const float* __restrict__ llr_a,
                 float* __restrict__ out) {
    __shared__ __half2 sA[32][CH + 1];
    __shared__ __half2 sB[32][CH + 1];

    const int c = blockIdx.x & (NCHUNK - 1);
    const int b = blockIdx.x >> 5;           // NCHUNK = 32
    const int tb = c * CH;
    const int w = threadIdx.x >> 5;
    const int L = threadIdx.x & 31;

    const float*  ch  = llr_ch + (size_t)b * (2 * TT);
    const float4* ch4 = (const float4*)ch;
    const float*  la  = llr_a + (size_t)b * TT;
    const float2* la2 = (const float2*)la;

    const __half2 HCLAMP = __float2half2_rn(60000.0f);

    if (w == 0) {
        // ---- alpha: warmup + chunk ----
        const int bit = L >> 4;
        const int p0 = (2 * L) & 31, p1 = p0 + 1;
        const float h0 = 0.5f * LOG2E * sg(2 * p0, 57, bit);
        const float h1 = 0.5f * LOG2E * sg(2 * p0, 27, bit);
        const float hb = 0.5f * LOG2E * (1.0f - 2.0f * (float)bit);

        float a0, a1;
        int gs;
        if (c == 0) { a0 = (L == 0) ? 1.0f : 0.0f; a1 = 0.0f; gs = 0; }
        else        { a0 = 1.0f / 64.0f; a1 = 1.0f / 64.0f;   gs = -WU; }

        for (int g = gs; g < CH; g += 4) {
            float r = __fdividef(1.0f, warp_max_pos(a0 + a1));

            const int tv = (tb + g) >> 1;
            float4 cA = __ldg(ch4 + tv);
            float4 cB = __ldg(ch4 + tv + 1);
            float2 dA = __ldg(la2 + tv);
            float2 dB = __ldg(la2 + tv + 1);
            float l0v[4] = {cA.x, cA.z, cB.x, cB.z};
            float l1v[4] = {cA.y, cA.w, cB.y, cB.w};
            float lav[4] = {dA.x, dA.y, dB.x, dB.y};
            float u0[4], u1[4];

#pragma unroll
            for (int k = 0; k < 4; k++) {
                u0[k] = a0; u1[k] = a1;
                float x = h0 * l0v[k];
                float y = h1 * l1v[k];
                float z = hb * lav[k];
                float spy = x + y, dmy = x - y;
                float A1 = ex2(z + spy);   // gamma(2p0,   bit)
                float A2 = ex2(z - spy);   // gamma(2p0+1, bit)
                float A3 = ex2(z + dmy);   // gamma(2p1,   bit)
                float A4 = ex2(z - dmy);   // gamma(2p1+1, bit)

                float pa0 = __shfl_sync(0xffffffffu, a0, p0);
                float pa1 = __shfl_sync(0xffffffffu, a1, p0);
                float qa0 = __shfl_sync(0xffffffffu, a0, p1);
                float qa1 = __shfl_sync(0xffffffffu, a1, p1);

                a0 = fmaf(A2, pa1, A1 * pa0);
                a1 = fmaf(A4, qa1, A3 * qa0);
            }
            if (g >= 0) {
#pragma unroll
                for (int k = 0; k < 4; k++)
                    sA[L][g + k] = __hmin2(__floats2half2_rn(u0[k] * r, u1[k] * r), HCLAMP);
            }
            a0 *= r; a1 *= r;
        }
    } else {
        // ---- beta: warmup + chunk (stride-32 layout: lane L = beta[L], beta[L+32]) ----
        const float x0L = 0.5f * LOG2E * sg(L, 57, 0);
        const float x1L = 0.5f * LOG2E * sg(L, 27, 0);
        const float xbL = 0.5f * LOG2E;
        const int srcA = L >> 1;
        const int srcB = 16 + (L >> 1);

        float b0 = 1.0f / 64.0f, b1 = 1.0f / 64.0f;
        const int ge = (c == NCHUNK - 1) ? CH : CH + WU;

        for (int g = ge - 4; g >= 0; g -= 4) {
            float r = __fdividef(1.0f, warp_max_pos(b0 + b1));

            const int tv = (tb + g) >> 1;
            float4 cA = __ldg(ch4 + tv);
            float4 cB = __ldg(ch4 + tv + 1);
            float2 dA = __ldg(la2 + tv);
            float2 dB = __ldg(la2 + tv + 1);
            float l0v[4] = {cA.x, cA.z, cB.x, cB.z};
            float l1v[4] = {cA.y, cA.w, cB.y, cB.w};
            float lav[4] = {dA.x, dA.y, dB.x, dB.y};
            float u0[4], u1[4];

#pragma unroll
            for (int kk = 0; kk < 4; kk++) {
                int k = 3 - kk;
                u0[k] = b0; u1[k] = b1;   // carry = beta_{t+1}[L], beta_{t+1}[L+32]
                float a = x0L * l0v[k];
                float b2 = fmaf(x1L, l1v[k], xbL * lav[k]);
                float sm = a + b2, df = a - b2;
                float Z   = ex2(sm);    // gamma(L, 0)
                float iZ  = ex2(-sm);   // gamma(L, 1)
                float c10 = ex2(-df);   // gamma(L+32, 0)
                float c11 = ex2(df);    // gamma(L+32, 1)

                float s0 = __shfl_sync(0xffffffffu, b0, srcA);
                float s1 = __shfl_sync(0xffffffffu, b1, srcA);
                float t0s = __shfl_sync(0xffffffffu, b0, srcB);
                float t1s = __shfl_sync(0xffffffffu, b1, srcB);

                b0 = fmaf(iZ, s1, Z * s0);
                b1 = fmaf(c11, t1s, c10 * t0s);
            }
            if (g < CH) {
#pragma unroll
                for (int k = 0; k < 4; k++)
                    sB[L][g + k] = __hmin2(__floats2half2_rn(u0[k] * r, u1[k] * r), HCLAMP);
            }
            b0 *= r; b1 *= r;
        }
    }

    __syncthreads();

    // ---- LLR: lane-per-t, no shuffles, no reductions; 32 t per warp ----
    {
        int tl = w * 32 + L;
        int t = tb + tl;
        float2 l01 = __ldg((const float2*)ch + t);
        float l0 = l01.x, l1 = l01.y;
        float laa = __ldg(la + t);

        float sp = 0.5f * LOG2E * (l0 + l1);
        float dm = 0.5f * LOG2E * (l0 - l1);
        float P   = ex2(sp);
        float iPv = ex2(-sp);
        float Q   = ex2(dm);
        float iQv = ex2(-dm);

        float S0 = 0.0f, S1 = 0.0f;
#pragma unroll
        for (int s = 0; s < 32; s++) {
            const int par0 = (__popc(s & 28)) & 1;   // sign of l0 term for state 2s
            const int par1 = (__popc(s & 13)) & 1;   // sign of l1 term for state 2s
            float X  = par0 ? (par1 ? iPv : iQv) : (par1 ? Q : P);
            float iX = par0 ? (par1 ? P : Q) : (par1 ? iQv : iPv);

            float2 a  = __half22float2(sA[s][tl]);
            float2 bb = __half22float2(sB[s][tl]);
            S0 = fmaf(bb.x, fmaf(a.y, iX, a.x * X), S0);
            S1 = fmaf(bb.y, fmaf(a.y, X, a.x * iX), S1);
        }
        out[(size_t)b * TT + t] = fmaf(LN2, lg2(S0) - lg2(S1), laa);
    }
}

extern "C" void kernel_launch(void* const* d_in, const int* in_sizes, int n_in,
                              void* d_out, int out_size) {
    const float* llr_ch = (const float*)d_in[0];   // [256, 4096]
    const float* llr_a  = (const float*)d_in[1];   // [256, 2048]
    float* out = (float*)d_out;                    // [256, 2048]

    bcjr_kernel<<<BB * NCHUNK, 64>>>(llr_ch, llr_a, out);
}

// round 13
// speedup vs baseline: 10.3973x; 1.0224x over previous
#include <cuda_runtime.h>
#include <cuda_fp16.h>
#include <cstdint>

#define TT 2048
#define BB 256
#define CH 64
#define WU 32
#define NCHUNK (TT / CH)   // 32

#define LOG2E 1.4426950408889634f
#define LN2   0.6931471805599453f

// Warp-uniform max of positive floats via integer redux (f32 redux not on sm_103).
__device__ __forceinline__ float warp_max_pos(float v) {
    unsigned r;
    asm volatile("redux.sync.max.u32 %0, %1, 0xffffffff;"
                 : "=r"(r) : "r"(__float_as_uint(v)));
    return __uint_as_float(r);
}

__device__ __forceinline__ float ex2(float x) {
    float y; asm("ex2.approx.f32 %0, %1;" : "=f"(y) : "f"(x)); return y;
}
__device__ __forceinline__ float lg2(float x) {
    float y; asm("lg2.approx.f32 %0, %1;" : "=f"(y) : "f"(x)); return y;
}

// sign = 1 - 2*((popc(s&mask) ^ b) & 1)
__device__ __forceinline__ float sg(int s, int mask, int b) {
    return 1.0f - 2.0f * (float)((__popc(s & mask) ^ b) & 1);
}

// ---------------------------------------------------------------------------
// One block per (batch, 64-step chunk), 2 warps.
// Warp0: alpha recursion (uniform seed WU steps early; exact delta for c=0).
// Warp1: beta recursion (uniform seed WU steps late; exact for last chunk).
// Normalization folded into the FIRST step of each 4-step group by adding
// -lg2(max) to that step's ex2 arguments (zero-lag). Carries stored raw
// (clamped) — LLR is invariant to per-t row scale. fp16 smem transposed
// [state][t] (stride CH+1); lane-per-t LLR with sign-group partial sums.
// ---------------------------------------------------------------------------
__global__ __launch_bounds__(64, 1)
void bcjr_kernel(const float* __restrict__ llr_ch, const float* __restrict__ llr_a,
                 float* __restrict__ out) {
    __shared__ __half2 sA[32][CH + 1];
    __shared__ __half2 sB[32][CH + 1];

    const int c = blockIdx.x & (NCHUNK - 1);
    const int b = blockIdx.x >> 5;           // NCHUNK = 32
    const int tb = c * CH;
    const int w = threadIdx.x >> 5;
    const int L = threadIdx.x & 31;

    const float*  ch  = llr_ch + (size_t)b * (2 * TT);
    const float4* ch4 = (const float4*)ch;
    const float*  la  = llr_a + (size_t)b * TT;
    const float2* la2 = (const float2*)la;

    const __half2 HCLAMP = __float2half2_rn(60000.0f);

    if (w == 0) {
        // ---- alpha: warmup + chunk ----
        const int bit = L >> 4;
        const int p0 = (2 * L) & 31, p1 = p0 + 1;
        const float h0 = 0.5f * LOG2E * sg(2 * p0, 57, bit);
        const float h1 = 0.5f * LOG2E * sg(2 * p0, 27, bit);
        const float hb = 0.5f * LOG2E * (1.0f - 2.0f * (float)bit);

        float a0, a1;
        int gs;
        if (c == 0) { a0 = (L == 0) ? 1.0f : 0.0f; a1 = 0.0f; gs = 0; }
        else        { a0 = 1.0f / 64.0f; a1 = 1.0f / 64.0f;   gs = -WU; }

        for (int g = gs; g < CH; g += 4) {
            float mlr = -lg2(warp_max_pos(a0 + a1));   // folded into step 0
            const bool st = (g >= 0);

            const int tv = (tb + g) >> 1;
            float4 cA = __ldg(ch4 + tv);
            float4 cB = __ldg(ch4 + tv + 1);
            float2 dA = __ldg(la2 + tv);
            float2 dB = __ldg(la2 + tv + 1);
            float l0v[4] = {cA.x, cA.z, cB.x, cB.z};
            float l1v[4] = {cA.y, cA.w, cB.y, cB.w};
            float lav[4] = {dA.x, dA.y, dB.x, dB.y};

#pragma unroll
            for (int k = 0; k < 4; k++) {
                if (st)
                    sA[L][g + k] = __hmin2(__floats2half2_rn(a0, a1), HCLAMP);

                float x = h0 * l0v[k];
                float y = h1 * l1v[k];
                float z = (k == 0) ? fmaf(hb, lav[k], mlr) : hb * lav[k];
                float spy = x + y, dmy = x - y;
                float A1 = ex2(z + spy);   // gamma(2p0,   bit) * (r if k==0)
                float A2 = ex2(z - spy);   // gamma(2p0+1, bit)
                float A3 = ex2(z + dmy);   // gamma(2p1,   bit)
                float A4 = ex2(z - dmy);   // gamma(2p1+1, bit)

                float pa0 = __shfl_sync(0xffffffffu, a0, p0);
                float pa1 = __shfl_sync(0xffffffffu, a1, p0);
                float qa0 = __shfl_sync(0xffffffffu, a0, p1);
                float qa1 = __shfl_sync(0xffffffffu, a1, p1);

                a0 = fmaf(A2, pa1, A1 * pa0);
                a1 = fmaf(A4, qa1, A3 * qa0);
            }
        }
    } else {
        // ---- beta: warmup + chunk (stride-32 layout: lane L = beta[L], beta[L+32]) ----
        const float x0L = 0.5f * LOG2E * sg(L, 57, 0);
        const float x1L = 0.5f * LOG2E * sg(L, 27, 0);
        const float xbL = 0.5f * LOG2E;
        const int srcA = L >> 1;
        const int srcB = 16 + (L >> 1);

        float b0 = 1.0f / 64.0f, b1 = 1.0f / 64.0f;
        const int ge = (c == NCHUNK - 1) ? CH : CH + WU;

        for (int g = ge - 4; g >= 0; g -= 4) {
            float lr = -lg2(warp_max_pos(b0 + b1));   // folded into first step
            const bool st = (g < CH);

            const int tv = (tb + g) >> 1;
            float4 cA = __ldg(ch4 + tv);
            float4 cB = __ldg(ch4 + tv + 1);
            float2 dA = __ldg(la2 + tv);
            float2 dB = __ldg(la2 + tv + 1);
            float l0v[4] = {cA.x, cA.z, cB.x, cB.z};
            float l1v[4] = {cA.y, cA.w, cB.y, cB.w};
            float lav[4] = {dA.x, dA.y, dB.x, dB.y};

#pragma unroll
            for (int kk = 0; kk < 4; kk++) {
                int k = 3 - kk;
                if (st)
                    sB[L][g + k] = __hmin2(__floats2half2_rn(b0, b1), HCLAMP);

                float a = x0L * l0v[k];
                float b2 = fmaf(x1L, l1v[k], xbL * lav[k]);
                float sm = a + b2, df = a - b2;
                float zp, zm, dp, dn;
                if (kk == 0) { zp = sm + lr; zm = lr - sm; dp = lr + df; dn = lr - df; }
                else         { zp = sm;      zm = -sm;      dp = df;      dn = -df;     }
                float Z   = ex2(zp);    // gamma(L, 0)    * (r on first step)
                float iZ  = ex2(zm);    // gamma(L, 1)
                float c10 = ex2(dn);    // gamma(L+32, 0)
                float c11 = ex2(dp);    // gamma(L+32, 1)

                float s0 = __shfl_sync(0xffffffffu, b0, srcA);
                float s1 = __shfl_sync(0xffffffffu, b1, srcA);
                float t0s = __shfl_sync(0xffffffffu, b0, srcB);
                float t1s = __shfl_sync(0xffffffffu, b1, srcB);

                b0 = fmaf(iZ, s1, Z * s0);
                b1 = fmaf(c11, t1s, c10 * t0s);
            }
        }
    }

    __syncthreads();

    // ---- LLR: lane-per-t, sign-group partial sums (X applied once per t) ----
    {
        int tl = w * 32 + L;
        int t = tb + tl;
        float2 l01 = __ldg((const float2*)ch + t);
        float l0 = l01.x, l1 = l01.y;
        float laa = __ldg(la + t);

        float sp = 0.5f * LOG2E * (l0 + l1);
        float dm = 0.5f * LOG2E * (l0 - l1);
        float P   = ex2(sp);
        float iPv = ex2(-sp);
        float Q   = ex2(dm);
        float iQv = ex2(-dm);

        float T0[4] = {0, 0, 0, 0};   // sum bb.x * a.x   per sign-group
        float T1[4] = {0, 0, 0, 0};   // sum bb.x * a.y
        float U0[4] = {0, 0, 0, 0};   // sum bb.y * a.x
        float U1[4] = {0, 0, 0, 0};   // sum bb.y * a.y
#pragma unroll
        for (int s = 0; s < 32; s++) {
            const int par0 = (__popc(s & 28)) & 1;   // sign of l0 term for state 2s
            const int par1 = (__popc(s & 13)) & 1;   // sign of l1 term for state 2s
            const int gI = par0 * 2 + par1;

            float2 a  = __half22float2(sA[s][tl]);
            float2 bb = __half22float2(sB[s][tl]);
            T0[gI] = fmaf(bb.x, a.x, T0[gI]);
            T1[gI] = fmaf(bb.x, a.y, T1[gI]);
            U0[gI] = fmaf(bb.y, a.x, U0[gI]);
            U1[gI] = fmaf(bb.y, a.y, U1[gI]);
        }
        // group: 0 -> X=P, 1 -> X=Q, 2 -> X=iQ, 3 -> X=iP
        float S0 = P   * (T0[0] + T1[3]) + iPv * (T1[0] + T0[3])
                 + Q   * (T0[1] + T1[2]) + iQv * (T1[1] + T0[2]);
        float S1 = P   * (U1[0] + U0[3]) + iPv * (U0[0] + U1[3])
                 + Q   * (U1[1] + U0[2]) + iQv * (U0[1] + U1[2]);

        out[(size_t)b * TT + t] = fmaf(LN2, lg2(S0) - lg2(S1), laa);
    }
}

extern "C" void kernel_launch(void* const* d_in, const int* in_sizes, int n_in,
                              void* d_out, int out_size) {
    const float* llr_ch = (const float*)d_in[0];   // [256, 4096]
    const float* llr_a  = (const float*)d_in[1];   // [256, 2048]
    float* out = (float*)d_out;                    // [256, 2048]

    bcjr_kernel<<<BB * NCHUNK, 64>>>(llr_ch, llr_a, out);
}